// round 2
// baseline (speedup 1.0000x reference)
#include <cuda_runtime.h>
#include <cstdint>
#include <cstddef>

#define D_IN  256
#define D_OUT 128
#define MAX_N 100000
#define MAX_E 1600000
#define SCAN_BLK 1024

// Scratch (device globals: no allocation allowed)
__device__ float g_h[(size_t)MAX_N * D_OUT];   // 51.2 MB
__device__ float g_a1[MAX_N];
__device__ float g_a2[MAX_N];
__device__ int   g_count[MAX_N];
__device__ int   g_excl[MAX_N];
__device__ int   g_bsum[SCAN_BLK];
__device__ int   g_boff[SCAN_BLK];
__device__ int   g_rowstart[MAX_N + 1];
__device__ int   g_pos[MAX_N];
__device__ int   g_scol[MAX_E];
__device__ float g_sw[MAX_E];

// ---------------- packed f32x2 helpers ----------------
__device__ __forceinline__ unsigned long long pack2(float x, float y) {
    unsigned long long r;
    asm("mov.b64 %0, {%1, %2};"
        : "=l"(r) : "r"(__float_as_uint(x)), "r"(__float_as_uint(y)));
    return r;
}
__device__ __forceinline__ void unpack2(unsigned long long v, float& x, float& y) {
    unsigned lo, hi;
    asm("mov.b64 {%0, %1}, %2;" : "=r"(lo), "=r"(hi) : "l"(v));
    x = __uint_as_float(lo);
    y = __uint_as_float(hi);
}
__device__ __forceinline__ void fma2(unsigned long long& d,
                                     unsigned long long a, unsigned long long b) {
    asm("fma.rn.f32x2 %0, %1, %2, %0;" : "+l"(d) : "l"(a), "l"(b));
}

// ---------------- GEMM: h = X@W + b ; a1 = h@wa1+ba1 ; a2 = h@wa2+ba2 --------
__global__ void __launch_bounds__(128) gemm_kernel(
    const float* __restrict__ A, const float* __restrict__ W,
    const float* __restrict__ bias,
    const float* __restrict__ wa1, const float* __restrict__ wa2,
    const float* __restrict__ ba1, const float* __restrict__ ba2,
    int M)
{
    __shared__ float As[16][64];    // A tile, transposed: As[k][row]
    __shared__ float Bs[16][128];   // W tile: Bs[k][col]

    const int tid  = threadIdx.x;
    const int tx   = tid & 15;   // col group: cols tx*8 .. tx*8+7
    const int ty   = tid >> 4;   // row group: rows ty*8 .. ty*8+7
    const int row0 = blockIdx.x * 64;

    unsigned long long acc[4][8];   // [row-pair][col]
#pragma unroll
    for (int p = 0; p < 4; p++)
#pragma unroll
        for (int j = 0; j < 8; j++) acc[p][j] = 0ull;

    for (int k0 = 0; k0 < D_IN; k0 += 16) {
#pragma unroll
        for (int i = 0; i < 2; i++) {
            int pos = tid + i * 128;          // 0..255
            int r   = pos >> 2;               // 0..63
            int kq  = pos & 3;                // quad of k
            float4 v = make_float4(0.f, 0.f, 0.f, 0.f);
            int gr = row0 + r;
            if (gr < M)
                v = *reinterpret_cast<const float4*>(A + (size_t)gr * D_IN + k0 + kq * 4);
            As[kq * 4 + 0][r] = v.x;
            As[kq * 4 + 1][r] = v.y;
            As[kq * 4 + 2][r] = v.z;
            As[kq * 4 + 3][r] = v.w;
        }
#pragma unroll
        for (int i = 0; i < 4; i++) {
            int pos = tid + i * 128;          // 0..511
            int kr  = pos >> 5;               // 0..15
            int c4  = pos & 31;               // 0..31
            *reinterpret_cast<float4*>(&Bs[kr][c4 * 4]) =
                *reinterpret_cast<const float4*>(W + (size_t)(k0 + kr) * D_OUT + c4 * 4);
        }
        __syncthreads();

#pragma unroll
        for (int k = 0; k < 16; k++) {
            const unsigned long long* ap =
                reinterpret_cast<const unsigned long long*>(&As[k][ty * 8]);
            unsigned long long av[4];
            av[0] = ap[0]; av[1] = ap[1]; av[2] = ap[2]; av[3] = ap[3];

            float4 b0 = *reinterpret_cast<const float4*>(&Bs[k][tx * 8]);
            float4 b1 = *reinterpret_cast<const float4*>(&Bs[k][tx * 8 + 4]);
            unsigned long long bb[8];
            bb[0] = pack2(b0.x, b0.x); bb[1] = pack2(b0.y, b0.y);
            bb[2] = pack2(b0.z, b0.z); bb[3] = pack2(b0.w, b0.w);
            bb[4] = pack2(b1.x, b1.x); bb[5] = pack2(b1.y, b1.y);
            bb[6] = pack2(b1.z, b1.z); bb[7] = pack2(b1.w, b1.w);

#pragma unroll
            for (int p = 0; p < 4; p++)
#pragma unroll
                for (int j = 0; j < 8; j++)
                    fma2(acc[p][j], av[p], bb[j]);
        }
        __syncthreads();
    }

    float bc[8], w1[8], w2[8];
#pragma unroll
    for (int j = 0; j < 8; j++) {
        int c = tx * 8 + j;
        bc[j] = bias[c];
        w1[j] = wa1[c];
        w2[j] = wa2[c];
    }

    float d1[8], d2[8];
#pragma unroll
    for (int p = 0; p < 4; p++) {
        float lo[8], hi[8];
#pragma unroll
        for (int j = 0; j < 8; j++) {
            unpack2(acc[p][j], lo[j], hi[j]);
            lo[j] += bc[j];
            hi[j] += bc[j];
        }
        int rlo = row0 + ty * 8 + 2 * p;
        if (rlo < M) {
            float4* hp = reinterpret_cast<float4*>(g_h + (size_t)rlo * D_OUT + tx * 8);
            hp[0] = make_float4(lo[0], lo[1], lo[2], lo[3]);
            hp[1] = make_float4(lo[4], lo[5], lo[6], lo[7]);
        }
        if (rlo + 1 < M) {
            float4* hp = reinterpret_cast<float4*>(g_h + (size_t)(rlo + 1) * D_OUT + tx * 8);
            hp[0] = make_float4(hi[0], hi[1], hi[2], hi[3]);
            hp[1] = make_float4(hi[4], hi[5], hi[6], hi[7]);
        }
        float s1l = 0.f, s2l = 0.f, s1h = 0.f, s2h = 0.f;
#pragma unroll
        for (int j = 0; j < 8; j++) {
            s1l += lo[j] * w1[j];
            s2l += lo[j] * w2[j];
            s1h += hi[j] * w1[j];
            s2h += hi[j] * w2[j];
        }
        d1[2 * p]     = s1l; d1[2 * p + 1] = s1h;
        d2[2 * p]     = s2l; d2[2 * p + 1] = s2h;
    }

    float bb1 = ba1[0], bb2 = ba2[0];
#pragma unroll
    for (int rr = 0; rr < 8; rr++) {
        float v1 = d1[rr], v2 = d2[rr];
#pragma unroll
        for (int o = 1; o < 16; o <<= 1) {
            v1 += __shfl_xor_sync(0xffffffffu, v1, o);
            v2 += __shfl_xor_sync(0xffffffffu, v2, o);
        }
        int gr = row0 + ty * 8 + rr;
        if (tx == 0 && gr < M) {
            g_a1[gr] = v1 + bb1;
            g_a2[gr] = v2 + bb2;
        }
    }
}

// ---------------- histogram of destination rows ----------------
__global__ void __launch_bounds__(256) hist_kernel(
    const int* __restrict__ row, int E)
{
    int e = blockIdx.x * blockDim.x + threadIdx.x;
    if (e < E) atomicAdd(&g_count[row[e]], 1);
}

// ---------------- 2-level exclusive scan ----------------
__device__ __forceinline__ void block_scan_1024(int v, int tid, int& excl, int& total)
{
    int lane = tid & 31, wid = tid >> 5;
    int x = v;
#pragma unroll
    for (int o = 1; o < 32; o <<= 1) {
        int y = __shfl_up_sync(0xffffffffu, x, o);
        if (lane >= o) x += y;
    }
    __shared__ int ws[32];
    if (lane == 31) ws[wid] = x;
    __syncthreads();
    if (wid == 0) {
        int s = ws[lane];
#pragma unroll
        for (int o = 1; o < 32; o <<= 1) {
            int y = __shfl_up_sync(0xffffffffu, s, o);
            if (lane >= o) s += y;
        }
        ws[lane] = s;
    }
    __syncthreads();
    int warp_off = (wid > 0) ? ws[wid - 1] : 0;
    int incl = warp_off + x;
    excl  = incl - v;
    total = ws[31];
}

__global__ void __launch_bounds__(SCAN_BLK) scan1_kernel(int n)
{
    int i = blockIdx.x * SCAN_BLK + threadIdx.x;
    int v = (i < n) ? g_count[i] : 0;
    int excl, total;
    block_scan_1024(v, threadIdx.x, excl, total);
    if (i < n) g_excl[i] = excl;
    if (threadIdx.x == 0) g_bsum[blockIdx.x] = total;
}

__global__ void __launch_bounds__(SCAN_BLK) scan2_kernel(int nb)
{
    int i = threadIdx.x;
    int v = (i < nb) ? g_bsum[i] : 0;
    int excl, total;
    block_scan_1024(v, threadIdx.x, excl, total);
    if (i < nb) g_boff[i] = excl;
}

__global__ void __launch_bounds__(SCAN_BLK) scan3_kernel(int n, int E)
{
    int i = blockIdx.x * SCAN_BLK + threadIdx.x;
    if (i < n) {
        int v = g_excl[i] + g_boff[blockIdx.x];
        g_rowstart[i] = v;
        g_pos[i]      = v;
        if (i == n - 1) g_rowstart[n] = E;
    }
}

// ---------------- scatter into CSR + edge scores ----------------
__global__ void __launch_bounds__(256) scatter_kernel(
    const int* __restrict__ row, const int* __restrict__ col, int E)
{
    int e = blockIdx.x * blockDim.x + threadIdx.x;
    if (e < E) {
        int r = row[e];
        int c = col[e];
        float s = g_a1[r] + g_a2[c];
        s = (s > 0.f) ? s : 0.01f * s;       // LeakyReLU(0.01)
        float w = __expf(s);                  // exp(s)/sum(exp(s)) == softmax(s)
        int p = atomicAdd(&g_pos[r], 1);
        g_scol[p] = c;
        g_sw[p]   = w;
    }
}

// ---------------- CSR gather SpMM: one warp per row ----------------
__global__ void __launch_bounds__(256) spmm_csr_kernel(
    float* __restrict__ out, int M)
{
    int r    = (blockIdx.x * blockDim.x + threadIdx.x) >> 5;
    int lane = threadIdx.x & 31;
    if (r >= M) return;

    int start = g_rowstart[r];
    int end   = g_rowstart[r + 1];

    float4 acc = make_float4(0.f, 0.f, 0.f, 0.f);

    if (end > start) {
        // pass 1: softmax denominator (register reduction, no atomics)
        float dsum = 0.f;
        for (int i = start + lane; i < end; i += 32) dsum += g_sw[i];
#pragma unroll
        for (int o = 16; o > 0; o >>= 1)
            dsum += __shfl_xor_sync(0xffffffffu, dsum, o);
        float inv = 1.0f / dsum;

        // pass 2: out[r] = sum att * h[col]
        const float4* h4 = reinterpret_cast<const float4*>(g_h);
        for (int base = start; base < end; base += 32) {
            int   n = end - base; if (n > 32) n = 32;
            int   c = 0;
            float w = 0.f;
            if (base + lane < end) {
                c = g_scol[base + lane];
                w = g_sw[base + lane];
            }
            for (int j = 0; j < n; j++) {
                int   cj = __shfl_sync(0xffffffffu, c, j);
                float wj = __shfl_sync(0xffffffffu, w, j);
                float4 v = h4[(size_t)cj * 32 + lane];
                acc.x = fmaf(wj, v.x, acc.x);
                acc.y = fmaf(wj, v.y, acc.y);
                acc.z = fmaf(wj, v.z, acc.z);
                acc.w = fmaf(wj, v.w, acc.w);
            }
        }
        acc.x *= inv; acc.y *= inv; acc.z *= inv; acc.w *= inv;
    }
    // single coalesced 512B store per row (also zeros empty rows)
    *reinterpret_cast<float4*>(out + (size_t)r * D_OUT + lane * 4) = acc;
}

// ---------------- launch ----------------
extern "C" void kernel_launch(void* const* d_in, const int* in_sizes, int n_in,
                              void* d_out, int out_size)
{
    const float* features = (const float*)d_in[0];
    const int*   ei       = (const int*)d_in[1];
    const float* W        = (const float*)d_in[2];
    const float* b        = (const float*)d_in[3];
    const float* wa1      = (const float*)d_in[4];
    const float* ba1      = (const float*)d_in[5];
    const float* wa2      = (const float*)d_in[6];
    const float* ba2      = (const float*)d_in[7];

    const int M = in_sizes[0] / D_IN;   // 100000
    const int E = in_sizes[1] / 2;      // 1600000
    float* out = (float*)d_out;

    const int* rowp = ei;
    const int* colp = ei + E;

    void* count_ptr = nullptr;
    cudaGetSymbolAddress(&count_ptr, g_count);
    cudaMemsetAsync(count_ptr, 0, (size_t)M * sizeof(int), 0);

    // histogram (independent of GEMM)
    int eblocks = (E + 255) / 256;
    hist_kernel<<<eblocks, 256>>>(rowp, E);

    // exclusive scan of row counts -> CSR row starts
    int nb = (M + SCAN_BLK - 1) / SCAN_BLK;
    scan1_kernel<<<nb, SCAN_BLK>>>(M);
    scan2_kernel<<<1, SCAN_BLK>>>(nb);
    scan3_kernel<<<nb, SCAN_BLK>>>(M, E);

    // GEMM + fused attention projections
    int gblocks = (M + 63) / 64;
    gemm_kernel<<<gblocks, 128>>>(features, W, b, wa1, wa2, ba1, ba2, M);

    // scatter (col, exp-weight) into CSR segments
    scatter_kernel<<<eblocks, 256>>>(rowp, colp, E);

    // gather SpMM: one warp per row, single store per row
    long long total_threads = (long long)M * 32;
    int mblocks = (int)((total_threads + 255) / 256);
    spmm_csr_kernel<<<mblocks, 256>>>(out, M);
}

// round 3
// speedup vs baseline: 2.2017x; 2.2017x over previous
#include <cuda_runtime.h>
#include <cstdint>
#include <cstddef>

#define D_IN  256
#define D_OUT 128
#define MAX_N 100000
#define MAX_E 1600000
#define SCAN_BLK 1024

// Scratch (device globals: no allocation allowed)
__device__ float g_h[(size_t)MAX_N * D_OUT];   // 51.2 MB
__device__ float g_a1[MAX_N];
__device__ float g_a2[MAX_N];
__device__ float g_Wt[D_OUT * D_IN];           // W transposed: [n][k]
__device__ int   g_count[MAX_N];
__device__ int   g_excl[MAX_N];
__device__ int   g_bsum[SCAN_BLK];
__device__ int   g_boff[SCAN_BLK];
__device__ int   g_rowstart[MAX_N + 1];
__device__ int   g_pos[MAX_N];
__device__ int   g_scol[MAX_E];
__device__ float g_sw[MAX_E];

// ---------------- ldmatrix / mma wrappers ----------------
__device__ __forceinline__ uint32_t smem_u32(const void* p) {
    return (uint32_t)__cvta_generic_to_shared(p);
}
__device__ __forceinline__ void ldsm_x4(uint32_t& r0, uint32_t& r1,
                                        uint32_t& r2, uint32_t& r3, uint32_t addr) {
    asm volatile("ldmatrix.sync.aligned.m8n8.x4.shared.b16 {%0,%1,%2,%3}, [%4];"
                 : "=r"(r0), "=r"(r1), "=r"(r2), "=r"(r3) : "r"(addr));
}
__device__ __forceinline__ void mma_tf32(float* d, const uint32_t* a, const uint32_t* b) {
    asm volatile(
        "mma.sync.aligned.m16n8k8.row.col.f32.tf32.tf32.f32 "
        "{%0,%1,%2,%3}, {%4,%5,%6,%7}, {%8,%9}, {%0,%1,%2,%3};"
        : "+f"(d[0]), "+f"(d[1]), "+f"(d[2]), "+f"(d[3])
        : "r"(a[0]), "r"(a[1]), "r"(a[2]), "r"(a[3]), "r"(b[0]), "r"(b[1]));
}

// ---------------- transpose W (256x128 -> 128x256) ----------------
__global__ void __launch_bounds__(256) transpose_w_kernel(const float* __restrict__ W)
{
    int idx = blockIdx.x * 256 + threadIdx.x;   // 32768 total
    if (idx < D_IN * D_OUT) {
        int k = idx / D_OUT;
        int n = idx % D_OUT;
        g_Wt[n * D_IN + k] = W[idx];
    }
}

// ---------------- tf32 tensor-core GEMM ----------------
// h = X@W + b (128-col), fused a1 = h@wa1+ba1, a2 = h@wa2+ba2 (atomic partial sums).
// BM=128, BN=128(full), BK=32. 256 threads = 8 warps (4 M x 2 N). Warp tile 32x64.
#define SMPAD 36
__global__ void __launch_bounds__(256) gemm_tf32_kernel(
    const float* __restrict__ A,
    const float* __restrict__ bias,
    const float* __restrict__ wa1, const float* __restrict__ wa2,
    const float* __restrict__ ba1, const float* __restrict__ ba2,
    int M)
{
    __shared__ float As[128][SMPAD];
    __shared__ float Bt[128][SMPAD];   // n-major: Bt[n][k]

    const int tid  = threadIdx.x;
    const int lane = tid & 31;
    const int wid  = tid >> 5;
    const int wm   = wid & 3;          // warp M index (0..3)
    const int wn   = wid >> 2;         // warp N index (0..1)
    const int row0 = blockIdx.x * 128;
    const int mrow = wm * 32;          // warp row offset in tile
    const int ncol = wn * 64;          // warp col offset

    const int grp = lane >> 3;         // ldmatrix fragment id
    const int rr  = lane & 7;

    float c[2][8][4];
#pragma unroll
    for (int mt = 0; mt < 2; mt++)
#pragma unroll
        for (int nt = 0; nt < 8; nt++)
#pragma unroll
            for (int i = 0; i < 4; i++) c[mt][nt][i] = 0.f;

    for (int k0 = 0; k0 < D_IN; k0 += 32) {
        // load A tile: 128 rows x 32 k (1024 float4, 4 per thread)
#pragma unroll
        for (int i = 0; i < 4; i++) {
            int idx = tid + i * 256;
            int r   = idx >> 3;
            int c4  = idx & 7;
            int gr  = row0 + r;
            float4 v = make_float4(0.f, 0.f, 0.f, 0.f);
            if (gr < M)
                v = *reinterpret_cast<const float4*>(A + (size_t)gr * D_IN + k0 + c4 * 4);
            *reinterpret_cast<float4*>(&As[r][c4 * 4]) = v;
        }
        // load Wt tile: 128 n x 32 k
#pragma unroll
        for (int i = 0; i < 4; i++) {
            int idx = tid + i * 256;
            int n   = idx >> 3;
            int c4  = idx & 7;
            *reinterpret_cast<float4*>(&Bt[n][c4 * 4]) =
                *reinterpret_cast<const float4*>(g_Wt + (size_t)n * D_IN + k0 + c4 * 4);
        }
        __syncthreads();

#pragma unroll
        for (int ks = 0; ks < 32; ks += 8) {
            // A fragments: 2 m-tiles of 16 rows
            uint32_t a[2][4];
#pragma unroll
            for (int mt = 0; mt < 2; mt++) {
                uint32_t addr = smem_u32(
                    &As[mrow + mt * 16 + rr + 8 * (grp & 1)][ks + 4 * (grp >> 1)]);
                ldsm_x4(a[mt][0], a[mt][1], a[mt][2], a[mt][3], addr);
            }
            // B fragments: 8 n-tiles (pairs via x4)
            uint32_t b[8][2];
#pragma unroll
            for (int p = 0; p < 4; p++) {
                int n0 = ncol + p * 16;
                uint32_t addr = smem_u32(
                    &Bt[n0 + rr + 8 * (grp >> 1)][ks + 4 * (grp & 1)]);
                ldsm_x4(b[2 * p][0], b[2 * p][1], b[2 * p + 1][0], b[2 * p + 1][1], addr);
            }
#pragma unroll
            for (int mt = 0; mt < 2; mt++)
#pragma unroll
                for (int nt = 0; nt < 8; nt++)
                    mma_tf32(c[mt][nt], a[mt], b[nt]);
        }
        __syncthreads();
    }

    // ---------------- epilogue ----------------
    const float ba1v = ba1[0];
    const float ba2v = ba2[0];
    const int qrow = lane >> 2;          // row within 16-tile (0..7)
    const int qcol = 2 * (lane & 3);     // col base within 8-tile

#pragma unroll
    for (int mt = 0; mt < 2; mt++) {
        int grlo = row0 + mrow + mt * 16 + qrow;
        int grhi = grlo + 8;
        float p1lo = 0.f, p2lo = 0.f, p1hi = 0.f, p2hi = 0.f;
#pragma unroll
        for (int nt = 0; nt < 8; nt++) {
            int gc = ncol + nt * 8 + qcol;
            float bc0 = bias[gc], bc1 = bias[gc + 1];
            float v0 = c[mt][nt][0] + bc0;
            float v1 = c[mt][nt][1] + bc1;
            float v2 = c[mt][nt][2] + bc0;
            float v3 = c[mt][nt][3] + bc1;
            if (grlo < M)
                *reinterpret_cast<float2*>(g_h + (size_t)grlo * D_OUT + gc) =
                    make_float2(v0, v1);
            if (grhi < M)
                *reinterpret_cast<float2*>(g_h + (size_t)grhi * D_OUT + gc) =
                    make_float2(v2, v3);
            float w1a = wa1[gc], w1b = wa1[gc + 1];
            float w2a = wa2[gc], w2b = wa2[gc + 1];
            p1lo += v0 * w1a + v1 * w1b;
            p2lo += v0 * w2a + v1 * w2b;
            p1hi += v2 * w1a + v3 * w1b;
            p2hi += v2 * w2a + v3 * w2b;
        }
        // reduce across the 4 lanes of the quad
#pragma unroll
        for (int o = 1; o < 4; o <<= 1) {
            p1lo += __shfl_xor_sync(0xffffffffu, p1lo, o);
            p2lo += __shfl_xor_sync(0xffffffffu, p2lo, o);
            p1hi += __shfl_xor_sync(0xffffffffu, p1hi, o);
            p2hi += __shfl_xor_sync(0xffffffffu, p2hi, o);
        }
        if ((lane & 3) == 0) {
            if (wn == 0) {    // bias added exactly once per row
                p1lo += ba1v; p2lo += ba2v;
                p1hi += ba1v; p2hi += ba2v;
            }
            if (grlo < M) {
                atomicAdd(&g_a1[grlo], p1lo);
                atomicAdd(&g_a2[grlo], p2lo);
            }
            if (grhi < M) {
                atomicAdd(&g_a1[grhi], p1hi);
                atomicAdd(&g_a2[grhi], p2hi);
            }
        }
    }
}

// ---------------- histogram of destination rows ----------------
__global__ void __launch_bounds__(256) hist_kernel(
    const int* __restrict__ row, int E)
{
    int e = blockIdx.x * blockDim.x + threadIdx.x;
    if (e < E) atomicAdd(&g_count[row[e]], 1);
}

// ---------------- 2-level exclusive scan ----------------
__device__ __forceinline__ void block_scan_1024(int v, int tid, int& excl, int& total)
{
    int lane = tid & 31, wid = tid >> 5;
    int x = v;
#pragma unroll
    for (int o = 1; o < 32; o <<= 1) {
        int y = __shfl_up_sync(0xffffffffu, x, o);
        if (lane >= o) x += y;
    }
    __shared__ int ws[32];
    if (lane == 31) ws[wid] = x;
    __syncthreads();
    if (wid == 0) {
        int s = ws[lane];
#pragma unroll
        for (int o = 1; o < 32; o <<= 1) {
            int y = __shfl_up_sync(0xffffffffu, s, o);
            if (lane >= o) s += y;
        }
        ws[lane] = s;
    }
    __syncthreads();
    int warp_off = (wid > 0) ? ws[wid - 1] : 0;
    int incl = warp_off + x;
    excl  = incl - v;
    total = ws[31];
}

__global__ void __launch_bounds__(SCAN_BLK) scan1_kernel(int n)
{
    int i = blockIdx.x * SCAN_BLK + threadIdx.x;
    int v = (i < n) ? g_count[i] : 0;
    int excl, total;
    block_scan_1024(v, threadIdx.x, excl, total);
    if (i < n) g_excl[i] = excl;
    if (threadIdx.x == 0) g_bsum[blockIdx.x] = total;
}

__global__ void __launch_bounds__(SCAN_BLK) scan2_kernel(int nb)
{
    int i = threadIdx.x;
    int v = (i < nb) ? g_bsum[i] : 0;
    int excl, total;
    block_scan_1024(v, threadIdx.x, excl, total);
    if (i < nb) g_boff[i] = excl;
}

__global__ void __launch_bounds__(SCAN_BLK) scan3_kernel(int n, int E)
{
    int i = blockIdx.x * SCAN_BLK + threadIdx.x;
    if (i < n) {
        int v = g_excl[i] + g_boff[blockIdx.x];
        g_rowstart[i] = v;
        g_pos[i]      = v;
        if (i == n - 1) g_rowstart[n] = E;
    }
}

// ---------------- scatter into CSR + edge scores ----------------
__global__ void __launch_bounds__(256) scatter_kernel(
    const int* __restrict__ row, const int* __restrict__ col, int E)
{
    int e = blockIdx.x * blockDim.x + threadIdx.x;
    if (e < E) {
        int r = row[e];
        int c = col[e];
        float s = g_a1[r] + g_a2[c];
        s = (s > 0.f) ? s : 0.01f * s;       // LeakyReLU(0.01)
        float w = __expf(s);                  // exp(s)/sum(exp(s)) == softmax(s)
        int p = atomicAdd(&g_pos[r], 1);
        g_scol[p] = c;
        g_sw[p]   = w;
    }
}

// ---------------- CSR gather SpMM: one warp per row, 4x unrolled ----------------
__global__ void __launch_bounds__(256) spmm_csr_kernel(
    float* __restrict__ out, int M)
{
    int r    = (blockIdx.x * blockDim.x + threadIdx.x) >> 5;
    int lane = threadIdx.x & 31;
    if (r >= M) return;

    int start = g_rowstart[r];
    int end   = g_rowstart[r + 1];

    float4 acc = make_float4(0.f, 0.f, 0.f, 0.f);

    if (end > start) {
        const float4* __restrict__ h4 = reinterpret_cast<const float4*>(g_h);
        float dsum = 0.f;   // identical in every lane (no reduce needed)

        for (int base = start; base < end; base += 32) {
            int   i = base + lane;
            int   cc = 0;
            float ww = 0.f;
            if (i < end) { cc = g_scol[i]; ww = g_sw[i]; }
            int n = end - base; if (n > 32) n = 32;

            int j = 0;
            for (; j + 4 <= n; j += 4) {
                int   c0 = __shfl_sync(0xffffffffu, cc, j);
                int   c1 = __shfl_sync(0xffffffffu, cc, j + 1);
                int   c2 = __shfl_sync(0xffffffffu, cc, j + 2);
                int   c3 = __shfl_sync(0xffffffffu, cc, j + 3);
                float w0 = __shfl_sync(0xffffffffu, ww, j);
                float w1 = __shfl_sync(0xffffffffu, ww, j + 1);
                float w2 = __shfl_sync(0xffffffffu, ww, j + 2);
                float w3 = __shfl_sync(0xffffffffu, ww, j + 3);
                float4 v0 = h4[(size_t)c0 * 32 + lane];
                float4 v1 = h4[(size_t)c1 * 32 + lane];
                float4 v2 = h4[(size_t)c2 * 32 + lane];
                float4 v3 = h4[(size_t)c3 * 32 + lane];
                dsum += w0 + w1 + w2 + w3;
                acc.x = fmaf(w0, v0.x, fmaf(w1, v1.x, fmaf(w2, v2.x, fmaf(w3, v3.x, acc.x))));
                acc.y = fmaf(w0, v0.y, fmaf(w1, v1.y, fmaf(w2, v2.y, fmaf(w3, v3.y, acc.y))));
                acc.z = fmaf(w0, v0.z, fmaf(w1, v1.z, fmaf(w2, v2.z, fmaf(w3, v3.z, acc.z))));
                acc.w = fmaf(w0, v0.w, fmaf(w1, v1.w, fmaf(w2, v2.w, fmaf(w3, v3.w, acc.w))));
            }
            for (; j < n; j++) {
                int   cj = __shfl_sync(0xffffffffu, cc, j);
                float wj = __shfl_sync(0xffffffffu, ww, j);
                float4 v = h4[(size_t)cj * 32 + lane];
                dsum += wj;
                acc.x = fmaf(wj, v.x, acc.x);
                acc.y = fmaf(wj, v.y, acc.y);
                acc.z = fmaf(wj, v.z, acc.z);
                acc.w = fmaf(wj, v.w, acc.w);
            }
        }
        float inv = 1.0f / dsum;
        acc.x *= inv; acc.y *= inv; acc.z *= inv; acc.w *= inv;
    }
    *reinterpret_cast<float4*>(out + (size_t)r * D_OUT + lane * 4) = acc;
}

// ---------------- launch ----------------
extern "C" void kernel_launch(void* const* d_in, const int* in_sizes, int n_in,
                              void* d_out, int out_size)
{
    const float* features = (const float*)d_in[0];
    const int*   ei       = (const int*)d_in[1];
    const float* W        = (const float*)d_in[2];
    const float* b        = (const float*)d_in[3];
    const float* wa1      = (const float*)d_in[4];
    const float* ba1      = (const float*)d_in[5];
    const float* wa2      = (const float*)d_in[6];
    const float* ba2      = (const float*)d_in[7];

    const int M = in_sizes[0] / D_IN;   // 100000
    const int E = in_sizes[1] / 2;      // 1600000
    float* out = (float*)d_out;

    const int* rowp = ei;
    const int* colp = ei + E;

    void* p = nullptr;
    cudaGetSymbolAddress(&p, g_count);
    cudaMemsetAsync(p, 0, (size_t)M * sizeof(int), 0);
    cudaGetSymbolAddress(&p, g_a1);
    cudaMemsetAsync(p, 0, (size_t)M * sizeof(float), 0);
    cudaGetSymbolAddress(&p, g_a2);
    cudaMemsetAsync(p, 0, (size_t)M * sizeof(float), 0);

    // W transpose for n-major smem staging
    transpose_w_kernel<<<(D_IN * D_OUT + 255) / 256, 256>>>(W);

    // histogram + scan (independent of GEMM)
    int eblocks = (E + 255) / 256;
    hist_kernel<<<eblocks, 256>>>(rowp, E);
    int nb = (M + SCAN_BLK - 1) / SCAN_BLK;
    scan1_kernel<<<nb, SCAN_BLK>>>(M);
    scan2_kernel<<<1, SCAN_BLK>>>(nb);
    scan3_kernel<<<nb, SCAN_BLK>>>(M, E);

    // tensor-core GEMM + fused attention projections
    int gblocks = (M + 127) / 128;
    gemm_tf32_kernel<<<gblocks, 256>>>(features, b, wa1, wa2, ba1, ba2, M);

    // scatter (col, exp-weight) into CSR segments
    scatter_kernel<<<eblocks, 256>>>(rowp, colp, E);

    // gather SpMM
    long long total_threads = (long long)M * 32;
    int mblocks = (int)((total_threads + 255) / 256);
    spmm_csr_kernel<<<mblocks, 256>>>(out, M);
}

// round 4
// speedup vs baseline: 2.4889x; 1.1305x over previous
#include <cuda_runtime.h>
#include <cstdint>
#include <cstddef>

#define D_IN  256
#define D_OUT 128
#define MAX_N 100000
#define MAX_E 1600000
#define SCAN_BLK 1024

// Scratch (device globals: no allocation allowed)
__device__ float  g_h[(size_t)MAX_N * D_OUT];   // 51.2 MB
__device__ float  g_a1[MAX_N];
__device__ float  g_a2[MAX_N];
__device__ float  g_Wt[D_OUT * D_IN];           // W transposed: [n][k]
__device__ int    g_count[MAX_N];
__device__ int    g_excl[MAX_N];
__device__ int    g_bsum[SCAN_BLK];
__device__ int    g_boff[SCAN_BLK];
__device__ int    g_rowstart[MAX_N + 1];
__device__ int    g_pos[MAX_N];
__device__ float2 g_scw[MAX_E];                 // packed (col-as-float-bits, expw)

// ---------------- ldmatrix / mma / cp.async wrappers ----------------
__device__ __forceinline__ uint32_t smem_u32(const void* p) {
    return (uint32_t)__cvta_generic_to_shared(p);
}
__device__ __forceinline__ void ldsm_x4(uint32_t& r0, uint32_t& r1,
                                        uint32_t& r2, uint32_t& r3, uint32_t addr) {
    asm volatile("ldmatrix.sync.aligned.m8n8.x4.shared.b16 {%0,%1,%2,%3}, [%4];"
                 : "=r"(r0), "=r"(r1), "=r"(r2), "=r"(r3) : "r"(addr));
}
__device__ __forceinline__ void mma_tf32(float* d, const uint32_t* a, const uint32_t* b) {
    asm volatile(
        "mma.sync.aligned.m16n8k8.row.col.f32.tf32.tf32.f32 "
        "{%0,%1,%2,%3}, {%4,%5,%6,%7}, {%8,%9}, {%0,%1,%2,%3};"
        : "+f"(d[0]), "+f"(d[1]), "+f"(d[2]), "+f"(d[3])
        : "r"(a[0]), "r"(a[1]), "r"(a[2]), "r"(a[3]), "r"(b[0]), "r"(b[1]));
}
__device__ __forceinline__ void cp_async16(uint32_t dst, const void* src, int src_bytes) {
    asm volatile("cp.async.cg.shared.global [%0], [%1], 16, %2;"
                 :: "r"(dst), "l"(src), "r"(src_bytes));
}
__device__ __forceinline__ void cp_commit() {
    asm volatile("cp.async.commit_group;");
}
template <int N>
__device__ __forceinline__ void cp_wait() {
    asm volatile("cp.async.wait_group %0;" :: "n"(N));
}

// ---------------- transpose W (256x128 -> 128x256) ----------------
__global__ void __launch_bounds__(256) transpose_w_kernel(const float* __restrict__ W)
{
    int idx = blockIdx.x * 256 + threadIdx.x;   // 32768 total
    if (idx < D_IN * D_OUT) {
        int k = idx / D_OUT;
        int n = idx % D_OUT;
        g_Wt[n * D_IN + k] = W[idx];
    }
}

// ---------------- tf32 tensor-core GEMM, 2-stage cp.async pipeline ----------
// h = X@W + b (128-col), fused a1 = h@wa1+ba1, a2 = h@wa2+ba2 (atomic partials).
// BM=128, BN=128(full), BK=32. 256 threads = 8 warps (4 M x 2 N). Warp tile 32x64.
#define SMPAD   36
#define TILE_F  (128 * SMPAD)        // floats per (A or B) stage
#define NKT     (D_IN / 32)          // 8 k-tiles

__global__ void __launch_bounds__(256) gemm_tf32_kernel(
    const float* __restrict__ A,
    const float* __restrict__ bias,
    const float* __restrict__ wa1, const float* __restrict__ wa2,
    const float* __restrict__ ba1, const float* __restrict__ ba2,
    int M)
{
    extern __shared__ float sm[];
    // layout: A stage0, A stage1, B stage0, B stage1
    float* Asm = sm;
    float* Bsm = sm + 2 * TILE_F;

    const int tid  = threadIdx.x;
    const int lane = tid & 31;
    const int wid  = tid >> 5;
    const int wm   = wid & 3;
    const int wn   = wid >> 2;
    const int row0 = blockIdx.x * 128;
    const int mrow = wm * 32;
    const int ncol = wn * 64;

    const int grp = lane >> 3;
    const int rr  = lane & 7;

    // per-thread load coords (4 x float4 each for A and B)
    int lr[4], lc[4];
#pragma unroll
    for (int i = 0; i < 4; i++) {
        int idx = tid + i * 256;
        lr[i] = idx >> 3;       // 0..127
        lc[i] = (idx & 7) * 4;  // 0..28
    }

    auto load_tiles = [&](int stage, int k0) {
        float* Ad = Asm + stage * TILE_F;
        float* Bd = Bsm + stage * TILE_F;
#pragma unroll
        for (int i = 0; i < 4; i++) {
            int gr = row0 + lr[i];
            int ok = (gr < M) ? 16 : 0;
            const float* src = A + (size_t)((gr < M) ? gr : 0) * D_IN + k0 + lc[i];
            cp_async16(smem_u32(Ad + lr[i] * SMPAD + lc[i]), src, ok);
        }
#pragma unroll
        for (int i = 0; i < 4; i++) {
            const float* src = g_Wt + (size_t)lr[i] * D_IN + k0 + lc[i];
            cp_async16(smem_u32(Bd + lr[i] * SMPAD + lc[i]), src, 16);
        }
        cp_commit();
    };

    float c[2][8][4];
#pragma unroll
    for (int mt = 0; mt < 2; mt++)
#pragma unroll
        for (int nt = 0; nt < 8; nt++)
#pragma unroll
            for (int i = 0; i < 4; i++) c[mt][nt][i] = 0.f;

    load_tiles(0, 0);

    for (int kt = 0; kt < NKT; kt++) {
        if (kt + 1 < NKT) {
            load_tiles((kt + 1) & 1, (kt + 1) * 32);
            cp_wait<1>();
        } else {
            cp_wait<0>();
        }
        __syncthreads();

        const float* As = Asm + (kt & 1) * TILE_F;
        const float* Bt = Bsm + (kt & 1) * TILE_F;

#pragma unroll
        for (int ks = 0; ks < 32; ks += 8) {
            uint32_t a[2][4];
#pragma unroll
            for (int mt = 0; mt < 2; mt++) {
                uint32_t addr = smem_u32(
                    As + (mrow + mt * 16 + rr + 8 * (grp & 1)) * SMPAD + ks + 4 * (grp >> 1));
                ldsm_x4(a[mt][0], a[mt][1], a[mt][2], a[mt][3], addr);
            }
            uint32_t b[8][2];
#pragma unroll
            for (int p = 0; p < 4; p++) {
                int n0 = ncol + p * 16;
                uint32_t addr = smem_u32(
                    Bt + (n0 + rr + 8 * (grp >> 1)) * SMPAD + ks + 4 * (grp & 1));
                ldsm_x4(b[2 * p][0], b[2 * p][1], b[2 * p + 1][0], b[2 * p + 1][1], addr);
            }
#pragma unroll
            for (int mt = 0; mt < 2; mt++)
#pragma unroll
                for (int nt = 0; nt < 8; nt++)
                    mma_tf32(c[mt][nt], a[mt], b[nt]);
        }
        __syncthreads();
    }

    // ---------------- epilogue ----------------
    const float ba1v = ba1[0];
    const float ba2v = ba2[0];
    const int qrow = lane >> 2;
    const int qcol = 2 * (lane & 3);

#pragma unroll
    for (int mt = 0; mt < 2; mt++) {
        int grlo = row0 + mrow + mt * 16 + qrow;
        int grhi = grlo + 8;
        float p1lo = 0.f, p2lo = 0.f, p1hi = 0.f, p2hi = 0.f;
#pragma unroll
        for (int nt = 0; nt < 8; nt++) {
            int gc = ncol + nt * 8 + qcol;
            float bc0 = bias[gc], bc1 = bias[gc + 1];
            float v0 = c[mt][nt][0] + bc0;
            float v1 = c[mt][nt][1] + bc1;
            float v2 = c[mt][nt][2] + bc0;
            float v3 = c[mt][nt][3] + bc1;
            if (grlo < M)
                *reinterpret_cast<float2*>(g_h + (size_t)grlo * D_OUT + gc) =
                    make_float2(v0, v1);
            if (grhi < M)
                *reinterpret_cast<float2*>(g_h + (size_t)grhi * D_OUT + gc) =
                    make_float2(v2, v3);
            float w1a = wa1[gc], w1b = wa1[gc + 1];
            float w2a = wa2[gc], w2b = wa2[gc + 1];
            p1lo += v0 * w1a + v1 * w1b;
            p2lo += v0 * w2a + v1 * w2b;
            p1hi += v2 * w1a + v3 * w1b;
            p2hi += v2 * w2a + v3 * w2b;
        }
#pragma unroll
        for (int o = 1; o < 4; o <<= 1) {
            p1lo += __shfl_xor_sync(0xffffffffu, p1lo, o);
            p2lo += __shfl_xor_sync(0xffffffffu, p2lo, o);
            p1hi += __shfl_xor_sync(0xffffffffu, p1hi, o);
            p2hi += __shfl_xor_sync(0xffffffffu, p2hi, o);
        }
        if ((lane & 3) == 0) {
            if (wn == 0) {
                p1lo += ba1v; p2lo += ba2v;
                p1hi += ba1v; p2hi += ba2v;
            }
            if (grlo < M) {
                atomicAdd(&g_a1[grlo], p1lo);
                atomicAdd(&g_a2[grlo], p2lo);
            }
            if (grhi < M) {
                atomicAdd(&g_a1[grhi], p1hi);
                atomicAdd(&g_a2[grhi], p2hi);
            }
        }
    }
}

// ---------------- histogram of destination rows (vectorized) ----------------
__global__ void __launch_bounds__(256) hist_kernel(
    const int* __restrict__ row, int E)
{
    int t = blockIdx.x * blockDim.x + threadIdx.x;
    int nq = E >> 2;
    if (t < nq) {
        int4 v = reinterpret_cast<const int4*>(row)[t];
        atomicAdd(&g_count[v.x], 1);
        atomicAdd(&g_count[v.y], 1);
        atomicAdd(&g_count[v.z], 1);
        atomicAdd(&g_count[v.w], 1);
    }
    int rem = nq * 4 + t;
    if (t < (E & 3) && rem < E) atomicAdd(&g_count[row[rem]], 1);
}

// ---------------- 2-level exclusive scan ----------------
__device__ __forceinline__ void block_scan_1024(int v, int tid, int& excl, int& total)
{
    int lane = tid & 31, wid = tid >> 5;
    int x = v;
#pragma unroll
    for (int o = 1; o < 32; o <<= 1) {
        int y = __shfl_up_sync(0xffffffffu, x, o);
        if (lane >= o) x += y;
    }
    __shared__ int ws[32];
    if (lane == 31) ws[wid] = x;
    __syncthreads();
    if (wid == 0) {
        int s = ws[lane];
#pragma unroll
        for (int o = 1; o < 32; o <<= 1) {
            int y = __shfl_up_sync(0xffffffffu, s, o);
            if (lane >= o) s += y;
        }
        ws[lane] = s;
    }
    __syncthreads();
    int warp_off = (wid > 0) ? ws[wid - 1] : 0;
    int incl = warp_off + x;
    excl  = incl - v;
    total = ws[31];
}

__global__ void __launch_bounds__(SCAN_BLK) scan1_kernel(int n)
{
    int i = blockIdx.x * SCAN_BLK + threadIdx.x;
    int v = (i < n) ? g_count[i] : 0;
    int excl, total;
    block_scan_1024(v, threadIdx.x, excl, total);
    if (i < n) g_excl[i] = excl;
    if (threadIdx.x == 0) g_bsum[blockIdx.x] = total;
}

__global__ void __launch_bounds__(SCAN_BLK) scan2_kernel(int nb)
{
    int i = threadIdx.x;
    int v = (i < nb) ? g_bsum[i] : 0;
    int excl, total;
    block_scan_1024(v, threadIdx.x, excl, total);
    if (i < nb) g_boff[i] = excl;
}

__global__ void __launch_bounds__(SCAN_BLK) scan3_kernel(int n, int E)
{
    int i = blockIdx.x * SCAN_BLK + threadIdx.x;
    if (i < n) {
        int v = g_excl[i] + g_boff[blockIdx.x];
        g_rowstart[i] = v;
        g_pos[i]      = v;
        if (i == n - 1) g_rowstart[n] = E;
    }
}

// ---------------- scatter into CSR + edge scores ----------------
__global__ void __launch_bounds__(256) scatter_kernel(
    const int* __restrict__ row, const int* __restrict__ col, int E)
{
    int e = blockIdx.x * blockDim.x + threadIdx.x;
    if (e < E) {
        int r = row[e];
        int c = col[e];
        float s = g_a1[r] + g_a2[c];
        s = (s > 0.f) ? s : 0.01f * s;       // LeakyReLU(0.01)
        float w = __expf(s);                  // exp(s)/sum(exp(s)) == softmax(s)
        int p = atomicAdd(&g_pos[r], 1);
        g_scw[p] = make_float2(__int_as_float(c), w);
    }
}

// ---------------- CSR gather SpMM: one warp per row, 4x unrolled ----------------
__global__ void __launch_bounds__(256) spmm_csr_kernel(
    float* __restrict__ out, int M)
{
    int r    = (blockIdx.x * blockDim.x + threadIdx.x) >> 5;
    int lane = threadIdx.x & 31;
    if (r >= M) return;

    int start = g_rowstart[r];
    int end   = g_rowstart[r + 1];

    float4 acc = make_float4(0.f, 0.f, 0.f, 0.f);

    if (end > start) {
        const float4* __restrict__ h4 = reinterpret_cast<const float4*>(g_h);
        float dsum = 0.f;   // identical in every lane (no reduce needed)

        for (int base = start; base < end; base += 32) {
            int   i = base + lane;
            int   cc = 0;
            float ww = 0.f;
            if (i < end) {
                float2 e = g_scw[i];
                cc = __float_as_int(e.x);
                ww = e.y;
            }
            int n = end - base; if (n > 32) n = 32;

            int j = 0;
            for (; j + 4 <= n; j += 4) {
                int   c0 = __shfl_sync(0xffffffffu, cc, j);
                int   c1 = __shfl_sync(0xffffffffu, cc, j + 1);
                int   c2 = __shfl_sync(0xffffffffu, cc, j + 2);
                int   c3 = __shfl_sync(0xffffffffu, cc, j + 3);
                float w0 = __shfl_sync(0xffffffffu, ww, j);
                float w1 = __shfl_sync(0xffffffffu, ww, j + 1);
                float w2 = __shfl_sync(0xffffffffu, ww, j + 2);
                float w3 = __shfl_sync(0xffffffffu, ww, j + 3);
                float4 v0 = h4[(size_t)c0 * 32 + lane];
                float4 v1 = h4[(size_t)c1 * 32 + lane];
                float4 v2 = h4[(size_t)c2 * 32 + lane];
                float4 v3 = h4[(size_t)c3 * 32 + lane];
                dsum += w0 + w1 + w2 + w3;
                acc.x = fmaf(w0, v0.x, fmaf(w1, v1.x, fmaf(w2, v2.x, fmaf(w3, v3.x, acc.x))));
                acc.y = fmaf(w0, v0.y, fmaf(w1, v1.y, fmaf(w2, v2.y, fmaf(w3, v3.y, acc.y))));
                acc.z = fmaf(w0, v0.z, fmaf(w1, v1.z, fmaf(w2, v2.z, fmaf(w3, v3.z, acc.z))));
                acc.w = fmaf(w0, v0.w, fmaf(w1, v1.w, fmaf(w2, v2.w, fmaf(w3, v3.w, acc.w))));
            }
            for (; j < n; j++) {
                int   cj = __shfl_sync(0xffffffffu, cc, j);
                float wj = __shfl_sync(0xffffffffu, ww, j);
                float4 v = h4[(size_t)cj * 32 + lane];
                dsum += wj;
                acc.x = fmaf(wj, v.x, acc.x);
                acc.y = fmaf(wj, v.y, acc.y);
                acc.z = fmaf(wj, v.z, acc.z);
                acc.w = fmaf(wj, v.w, acc.w);
            }
        }
        float inv = 1.0f / dsum;
        acc.x *= inv; acc.y *= inv; acc.z *= inv; acc.w *= inv;
    }
    *reinterpret_cast<float4*>(out + (size_t)r * D_OUT + lane * 4) = acc;
}

// ---------------- launch ----------------
extern "C" void kernel_launch(void* const* d_in, const int* in_sizes, int n_in,
                              void* d_out, int out_size)
{
    const float* features = (const float*)d_in[0];
    const int*   ei       = (const int*)d_in[1];
    const float* W        = (const float*)d_in[2];
    const float* b        = (const float*)d_in[3];
    const float* wa1      = (const float*)d_in[4];
    const float* ba1      = (const float*)d_in[5];
    const float* wa2      = (const float*)d_in[6];
    const float* ba2      = (const float*)d_in[7];

    const int M = in_sizes[0] / D_IN;   // 100000
    const int E = in_sizes[1] / 2;      // 1600000
    float* out = (float*)d_out;

    const int* rowp = ei;
    const int* colp = ei + E;

    void* p = nullptr;
    cudaGetSymbolAddress(&p, g_count);
    cudaMemsetAsync(p, 0, (size_t)M * sizeof(int), 0);
    cudaGetSymbolAddress(&p, g_a1);
    cudaMemsetAsync(p, 0, (size_t)M * sizeof(float), 0);
    cudaGetSymbolAddress(&p, g_a2);
    cudaMemsetAsync(p, 0, (size_t)M * sizeof(float), 0);

    // W transpose for n-major smem staging
    transpose_w_kernel<<<(D_IN * D_OUT + 255) / 256, 256>>>(W);

    // histogram + scan (independent of GEMM)
    int eblocks = (E + 255) / 256;
    hist_kernel<<<(E / 4 + 255) / 256, 256>>>(rowp, E);
    int nb = (M + SCAN_BLK - 1) / SCAN_BLK;
    scan1_kernel<<<nb, SCAN_BLK>>>(M);
    scan2_kernel<<<1, SCAN_BLK>>>(nb);
    scan3_kernel<<<nb, SCAN_BLK>>>(M, E);

    // tensor-core GEMM + fused attention projections (2-stage cp.async)
    static const size_t smem_bytes = 4 * TILE_F * sizeof(float);   // 73728
    cudaFuncSetAttribute(gemm_tf32_kernel,
                         cudaFuncAttributeMaxDynamicSharedMemorySize,
                         (int)smem_bytes);
    int gblocks = (M + 127) / 128;
    gemm_tf32_kernel<<<gblocks, 256, smem_bytes>>>(features, b, wa1, wa2, ba1, ba2, M);

    // scatter (col, exp-weight) into CSR segments
    scatter_kernel<<<eblocks, 256>>>(rowp, colp, E);

    // gather SpMM
    long long total_threads = (long long)M * 32;
    int mblocks = (int)((total_threads + 255) / 256);
    spmm_csr_kernel<<<mblocks, 256>>>(out, M);
}

// round 6
// speedup vs baseline: 2.7541x; 1.1065x over previous
#include <cuda_runtime.h>
#include <cuda_fp16.h>
#include <cstdint>
#include <cstddef>

#define D_IN  256
#define D_OUT 128
#define MAX_N 100000
#define MAX_E 1600000
#define SCAN_BLK 1024
#define VALID_FLAG (1u << 30)

// Scratch (device globals: no allocation allowed)
__device__ uint32_t g_hh[(size_t)MAX_N * (D_OUT / 2)];  // h as fp16x2, 25.6 MB
__device__ float  g_a1[MAX_N];
__device__ float  g_a2[MAX_N];
__device__ float  g_Wt[D_OUT * D_IN];           // W transposed + pre-rounded to tf32
__device__ int    g_count[MAX_N];
__device__ unsigned g_bsum[128];                // block totals | VALID_FLAG
__device__ int    g_rowstart[MAX_N + 1];
__device__ int    g_pos[MAX_N];
__device__ float2 g_scw[MAX_E];                 // packed (col-as-float-bits, expw)

// ---------------- ldmatrix / mma / cp.async wrappers ----------------
__device__ __forceinline__ uint32_t smem_u32(const void* p) {
    return (uint32_t)__cvta_generic_to_shared(p);
}
__device__ __forceinline__ void ldsm_x4(uint32_t& r0, uint32_t& r1,
                                        uint32_t& r2, uint32_t& r3, uint32_t addr) {
    asm volatile("ldmatrix.sync.aligned.m8n8.x4.shared.b16 {%0,%1,%2,%3}, [%4];"
                 : "=r"(r0), "=r"(r1), "=r"(r2), "=r"(r3) : "r"(addr));
}
__device__ __forceinline__ void mma_tf32(float* d, const uint32_t* a, const uint32_t* b) {
    asm volatile(
        "mma.sync.aligned.m16n8k8.row.col.f32.tf32.tf32.f32 "
        "{%0,%1,%2,%3}, {%4,%5,%6,%7}, {%8,%9}, {%0,%1,%2,%3};"
        : "+f"(d[0]), "+f"(d[1]), "+f"(d[2]), "+f"(d[3])
        : "r"(a[0]), "r"(a[1]), "r"(a[2]), "r"(a[3]), "r"(b[0]), "r"(b[1]));
}
__device__ __forceinline__ uint32_t tf32_rna(float f) {
    uint32_t r;
    asm("cvt.rna.tf32.f32 %0, %1;" : "=r"(r) : "f"(f));
    return r;
}
__device__ __forceinline__ uint32_t f16x2_rn(float lo, float hi) {
    uint32_t r;   // %1 -> high half, %2 -> low half
    asm("cvt.rn.f16x2.f32 %0, %1, %2;" : "=r"(r) : "f"(hi), "f"(lo));
    return r;
}
__device__ __forceinline__ void cp_async16(uint32_t dst, const void* src, int src_bytes) {
    asm volatile("cp.async.cg.shared.global [%0], [%1], 16, %2;"
                 :: "r"(dst), "l"(src), "r"(src_bytes));
}
__device__ __forceinline__ void cp_commit() {
    asm volatile("cp.async.commit_group;");
}
template <int N>
__device__ __forceinline__ void cp_wait() {
    asm volatile("cp.async.wait_group %0;" :: "n"(N));
}

// ---------------- transpose W + pre-round to tf32 (rna, unbiased) -----------
__global__ void __launch_bounds__(256) transpose_w_kernel(const float* __restrict__ W)
{
    int idx = blockIdx.x * 256 + threadIdx.x;   // 32768 total
    if (idx < D_IN * D_OUT) {
        int k = idx / D_OUT;
        int n = idx % D_OUT;
        uint32_t t = tf32_rna(W[idx]);
        g_Wt[n * D_IN + k] = __uint_as_float(t);
    }
}

// ---------------- tf32 tensor-core GEMM, 2-stage cp.async pipeline ----------
// h = X@W + b -> fp16; fused a1 = h@wa1+ba1, a2 = h@wa2+ba2 (atomic partials).
#define SMPAD   36
#define TILE_F  (128 * SMPAD)
#define NKT     (D_IN / 32)

__global__ void __launch_bounds__(256) gemm_tf32_kernel(
    const float* __restrict__ A,
    const float* __restrict__ bias,
    const float* __restrict__ wa1, const float* __restrict__ wa2,
    const float* __restrict__ ba1, const float* __restrict__ ba2,
    int M)
{
    extern __shared__ float sm[];
    float* Asm = sm;
    float* Bsm = sm + 2 * TILE_F;

    const int tid  = threadIdx.x;
    const int lane = tid & 31;
    const int wid  = tid >> 5;
    const int wm   = wid & 3;
    const int wn   = wid >> 2;
    const int row0 = blockIdx.x * 128;
    const int mrow = wm * 32;
    const int ncol = wn * 64;

    const int grp = lane >> 3;
    const int rr  = lane & 7;

    int lr[4], lc[4];
#pragma unroll
    for (int i = 0; i < 4; i++) {
        int idx = tid + i * 256;
        lr[i] = idx >> 3;
        lc[i] = (idx & 7) * 4;
    }

    auto load_tiles = [&](int stage, int k0) {
        float* Ad = Asm + stage * TILE_F;
        float* Bd = Bsm + stage * TILE_F;
#pragma unroll
        for (int i = 0; i < 4; i++) {
            int gr = row0 + lr[i];
            int ok = (gr < M) ? 16 : 0;
            const float* src = A + (size_t)((gr < M) ? gr : 0) * D_IN + k0 + lc[i];
            cp_async16(smem_u32(Ad + lr[i] * SMPAD + lc[i]), src, ok);
        }
#pragma unroll
        for (int i = 0; i < 4; i++) {
            const float* src = g_Wt + (size_t)lr[i] * D_IN + k0 + lc[i];
            cp_async16(smem_u32(Bd + lr[i] * SMPAD + lc[i]), src, 16);
        }
        cp_commit();
    };

    float c[2][8][4];
#pragma unroll
    for (int mt = 0; mt < 2; mt++)
#pragma unroll
        for (int nt = 0; nt < 8; nt++)
#pragma unroll
            for (int i = 0; i < 4; i++) c[mt][nt][i] = 0.f;

    load_tiles(0, 0);

    for (int kt = 0; kt < NKT; kt++) {
        if (kt + 1 < NKT) {
            load_tiles((kt + 1) & 1, (kt + 1) * 32);
            cp_wait<1>();
        } else {
            cp_wait<0>();
        }
        __syncthreads();

        const float* As = Asm + (kt & 1) * TILE_F;
        const float* Bt = Bsm + (kt & 1) * TILE_F;

#pragma unroll
        for (int ks = 0; ks < 32; ks += 8) {
            uint32_t a[2][4];
#pragma unroll
            for (int mt = 0; mt < 2; mt++) {
                uint32_t addr = smem_u32(
                    As + (mrow + mt * 16 + rr + 8 * (grp & 1)) * SMPAD + ks + 4 * (grp >> 1));
                ldsm_x4(a[mt][0], a[mt][1], a[mt][2], a[mt][3], addr);
                // unbiased rounding of A operands (kills tf32 truncation bias)
#pragma unroll
                for (int q = 0; q < 4; q++)
                    a[mt][q] = tf32_rna(__uint_as_float(a[mt][q]));
            }
            uint32_t b[8][2];   // B pre-rounded in transpose kernel
#pragma unroll
            for (int p = 0; p < 4; p++) {
                int n0 = ncol + p * 16;
                uint32_t addr = smem_u32(
                    Bt + (n0 + rr + 8 * (grp >> 1)) * SMPAD + ks + 4 * (grp & 1));
                ldsm_x4(b[2 * p][0], b[2 * p][1], b[2 * p + 1][0], b[2 * p + 1][1], addr);
            }
#pragma unroll
            for (int mt = 0; mt < 2; mt++)
#pragma unroll
                for (int nt = 0; nt < 8; nt++)
                    mma_tf32(c[mt][nt], a[mt], b[nt]);
        }
        __syncthreads();
    }

    // ---------------- epilogue: fp16 h store + fused a1/a2 ----------------
    const float ba1v = ba1[0];
    const float ba2v = ba2[0];
    const int qrow = lane >> 2;
    const int qcol = 2 * (lane & 3);

#pragma unroll
    for (int mt = 0; mt < 2; mt++) {
        int grlo = row0 + mrow + mt * 16 + qrow;
        int grhi = grlo + 8;
        float p1lo = 0.f, p2lo = 0.f, p1hi = 0.f, p2hi = 0.f;
#pragma unroll
        for (int nt = 0; nt < 8; nt++) {
            int gc = ncol + nt * 8 + qcol;
            float bc0 = bias[gc], bc1 = bias[gc + 1];
            float v0 = c[mt][nt][0] + bc0;
            float v1 = c[mt][nt][1] + bc1;
            float v2 = c[mt][nt][2] + bc0;
            float v3 = c[mt][nt][3] + bc1;
            if (grlo < M)
                g_hh[(size_t)grlo * (D_OUT / 2) + gc / 2] = f16x2_rn(v0, v1);
            if (grhi < M)
                g_hh[(size_t)grhi * (D_OUT / 2) + gc / 2] = f16x2_rn(v2, v3);
            float w1a = wa1[gc], w1b = wa1[gc + 1];
            float w2a = wa2[gc], w2b = wa2[gc + 1];
            p1lo += v0 * w1a + v1 * w1b;
            p2lo += v0 * w2a + v1 * w2b;
            p1hi += v2 * w1a + v3 * w1b;
            p2hi += v2 * w2a + v3 * w2b;
        }
#pragma unroll
        for (int o = 1; o < 4; o <<= 1) {
            p1lo += __shfl_xor_sync(0xffffffffu, p1lo, o);
            p2lo += __shfl_xor_sync(0xffffffffu, p2lo, o);
            p1hi += __shfl_xor_sync(0xffffffffu, p1hi, o);
            p2hi += __shfl_xor_sync(0xffffffffu, p2hi, o);
        }
        if ((lane & 3) == 0) {
            if (wn == 0) {
                p1lo += ba1v; p2lo += ba2v;
                p1hi += ba1v; p2hi += ba2v;
            }
            if (grlo < M) {
                atomicAdd(&g_a1[grlo], p1lo);
                atomicAdd(&g_a2[grlo], p2lo);
            }
            if (grhi < M) {
                atomicAdd(&g_a1[grhi], p1hi);
                atomicAdd(&g_a2[grhi], p2hi);
            }
        }
    }
}

// ---------------- histogram of destination rows (vectorized) ----------------
__global__ void __launch_bounds__(256) hist_kernel(
    const int* __restrict__ row, int E)
{
    int t = blockIdx.x * blockDim.x + threadIdx.x;
    int nq = E >> 2;
    if (t < nq) {
        int4 v = reinterpret_cast<const int4*>(row)[t];
        atomicAdd(&g_count[v.x], 1);
        atomicAdd(&g_count[v.y], 1);
        atomicAdd(&g_count[v.z], 1);
        atomicAdd(&g_count[v.w], 1);
    }
    int rem = nq * 4 + t;
    if (t < (E & 3) && rem < E) atomicAdd(&g_count[row[rem]], 1);
}

// ---------------- fused single-pass exclusive scan (inter-block lookback) ----
// nb <= 98 blocks, all resident simultaneously -> spin-wait is deadlock-free.
__device__ __forceinline__ void block_scan_1024(int v, int tid, int& excl, int& total)
{
    int lane = tid & 31, wid = tid >> 5;
    int x = v;
#pragma unroll
    for (int o = 1; o < 32; o <<= 1) {
        int y = __shfl_up_sync(0xffffffffu, x, o);
        if (lane >= o) x += y;
    }
    __shared__ int ws[32];
    if (lane == 31) ws[wid] = x;
    __syncthreads();
    if (wid == 0) {
        int s = ws[lane];
#pragma unroll
        for (int o = 1; o < 32; o <<= 1) {
            int y = __shfl_up_sync(0xffffffffu, s, o);
            if (lane >= o) s += y;
        }
        ws[lane] = s;
    }
    __syncthreads();
    int warp_off = (wid > 0) ? ws[wid - 1] : 0;
    int incl = warp_off + x;
    excl  = incl - v;
    total = ws[31];
}

__global__ void __launch_bounds__(SCAN_BLK) scan_fused_kernel(int n, int E)
{
    int i = blockIdx.x * SCAN_BLK + threadIdx.x;
    int v = (i < n) ? g_count[i] : 0;
    int excl, total;
    block_scan_1024(v, threadIdx.x, excl, total);

    // publish this block's total
    if (threadIdx.x == 0)
        atomicExch(&g_bsum[blockIdx.x], (unsigned)total | VALID_FLAG);

    // gather predecessor totals (thread t polls predecessor t)
    int part = 0;
    if (threadIdx.x < blockIdx.x) {
        unsigned w;
        do { w = atomicAdd(&g_bsum[threadIdx.x], 0u); } while (!(w & VALID_FLAG));
        part = (int)(w & (VALID_FLAG - 1));
    }
    // block-reduce part
    int lane = threadIdx.x & 31, wid = threadIdx.x >> 5;
#pragma unroll
    for (int o = 16; o > 0; o >>= 1)
        part += __shfl_xor_sync(0xffffffffu, part, o);
    __shared__ int rs[32];
    __syncthreads();             // protect ws reuse in block_scan
    if (lane == 0) rs[wid] = part;
    __syncthreads();
    if (wid == 0) {
        int s = rs[lane];
#pragma unroll
        for (int o = 16; o > 0; o >>= 1)
            s += __shfl_xor_sync(0xffffffffu, s, o);
        rs[0] = s;
    }
    __syncthreads();
    int offset = rs[0];

    if (i < n) {
        int vv = excl + offset;
        g_rowstart[i] = vv;
        g_pos[i]      = vv;
        if (i == n - 1) g_rowstart[n] = E;
    }
}

// ---------------- scatter into CSR + edge scores ----------------
__global__ void __launch_bounds__(256) scatter_kernel(
    const int* __restrict__ row, const int* __restrict__ col, int E)
{
    int e = blockIdx.x * blockDim.x + threadIdx.x;
    if (e < E) {
        int r = row[e];
        int c = col[e];
        float s = g_a1[r] + g_a2[c];
        s = (s > 0.f) ? s : 0.01f * s;       // LeakyReLU(0.01)
        float w = __expf(s);                  // exp(s)/sum(exp(s)) == softmax(s)
        int p = atomicAdd(&g_pos[r], 1);
        g_scw[p] = make_float2(__int_as_float(c), w);
    }
}

// ---------------- CSR gather SpMM: one warp per row, fp16 h ----------------
__device__ __forceinline__ void f16x2_unpack(uint32_t u, float& lo, float& hi) {
    __half2 h = *reinterpret_cast<__half2*>(&u);
    float2 f = __half22float2(h);
    lo = f.x;
    hi = f.y;
}

__global__ void __launch_bounds__(256) spmm_csr_kernel(
    float* __restrict__ out, int M)
{
    int r    = (blockIdx.x * blockDim.x + threadIdx.x) >> 5;
    int lane = threadIdx.x & 31;
    if (r >= M) return;

    int start = g_rowstart[r];
    int end   = g_rowstart[r + 1];

    float4 acc = make_float4(0.f, 0.f, 0.f, 0.f);

    if (end > start) {
        const uint2* __restrict__ h2 = reinterpret_cast<const uint2*>(g_hh);
        float dsum = 0.f;   // identical in every lane

        for (int base = start; base < end; base += 32) {
            int   i = base + lane;
            int   cc = 0;
            float ww = 0.f;
            if (i < end) {
                float2 e = g_scw[i];
                cc = __float_as_int(e.x);
                ww = e.y;
            }
            int n = end - base; if (n > 32) n = 32;

            int j = 0;
            for (; j + 4 <= n; j += 4) {
                int   c0 = __shfl_sync(0xffffffffu, cc, j);
                int   c1 = __shfl_sync(0xffffffffu, cc, j + 1);
                int   c2 = __shfl_sync(0xffffffffu, cc, j + 2);
                int   c3 = __shfl_sync(0xffffffffu, cc, j + 3);
                float w0 = __shfl_sync(0xffffffffu, ww, j);
                float w1 = __shfl_sync(0xffffffffu, ww, j + 1);
                float w2 = __shfl_sync(0xffffffffu, ww, j + 2);
                float w3 = __shfl_sync(0xffffffffu, ww, j + 3);
                uint2 u0 = h2[(size_t)c0 * 32 + lane];
                uint2 u1 = h2[(size_t)c1 * 32 + lane];
                uint2 u2 = h2[(size_t)c2 * 32 + lane];
                uint2 u3 = h2[(size_t)c3 * 32 + lane];
                dsum += w0 + w1 + w2 + w3;
                float ax, ay, az, aw;
                f16x2_unpack(u0.x, ax, ay); f16x2_unpack(u0.y, az, aw);
                acc.x = fmaf(w0, ax, acc.x); acc.y = fmaf(w0, ay, acc.y);
                acc.z = fmaf(w0, az, acc.z); acc.w = fmaf(w0, aw, acc.w);
                f16x2_unpack(u1.x, ax, ay); f16x2_unpack(u1.y, az, aw);
                acc.x = fmaf(w1, ax, acc.x); acc.y = fmaf(w1, ay, acc.y);
                acc.z = fmaf(w1, az, acc.z); acc.w = fmaf(w1, aw, acc.w);
                f16x2_unpack(u2.x, ax, ay); f16x2_unpack(u2.y, az, aw);
                acc.x = fmaf(w2, ax, acc.x); acc.y = fmaf(w2, ay, acc.y);
                acc.z = fmaf(w2, az, acc.z); acc.w = fmaf(w2, aw, acc.w);
                f16x2_unpack(u3.x, ax, ay); f16x2_unpack(u3.y, az, aw);
                acc.x = fmaf(w3, ax, acc.x); acc.y = fmaf(w3, ay, acc.y);
                acc.z = fmaf(w3, az, acc.z); acc.w = fmaf(w3, aw, acc.w);
            }
            for (; j < n; j++) {
                int   cj = __shfl_sync(0xffffffffu, cc, j);
                float wj = __shfl_sync(0xffffffffu, ww, j);
                uint2 u = h2[(size_t)cj * 32 + lane];
                dsum += wj;
                float ax, ay, az, aw;
                f16x2_unpack(u.x, ax, ay); f16x2_unpack(u.y, az, aw);
                acc.x = fmaf(wj, ax, acc.x); acc.y = fmaf(wj, ay, acc.y);
                acc.z = fmaf(wj, az, acc.z); acc.w = fmaf(wj, aw, acc.w);
            }
        }
        float inv = 1.0f / dsum;
        acc.x *= inv; acc.y *= inv; acc.z *= inv; acc.w *= inv;
    }
    *reinterpret_cast<float4*>(out + (size_t)r * D_OUT + lane * 4) = acc;
}

// ---------------- launch ----------------
extern "C" void kernel_launch(void* const* d_in, const int* in_sizes, int n_in,
                              void* d_out, int out_size)
{
    const float* features = (const float*)d_in[0];
    const int*   ei       = (const int*)d_in[1];
    const float* W        = (const float*)d_in[2];
    const float* b        = (const float*)d_in[3];
    const float* wa1      = (const float*)d_in[4];
    const float* ba1      = (const float*)d_in[5];
    const float* wa2      = (const float*)d_in[6];
    const float* ba2      = (const float*)d_in[7];

    const int M = in_sizes[0] / D_IN;   // 100000
    const int E = in_sizes[1] / 2;      // 1600000
    float* out = (float*)d_out;

    const int* rowp = ei;
    const int* colp = ei + E;

    void* p = nullptr;
    cudaGetSymbolAddress(&p, g_count);
    cudaMemsetAsync(p, 0, (size_t)M * sizeof(int), 0);
    cudaGetSymbolAddress(&p, g_bsum);
    cudaMemsetAsync(p, 0, 128 * sizeof(unsigned), 0);
    cudaGetSymbolAddress(&p, g_a1);
    cudaMemsetAsync(p, 0, (size_t)M * sizeof(float), 0);
    cudaGetSymbolAddress(&p, g_a2);
    cudaMemsetAsync(p, 0, (size_t)M * sizeof(float), 0);

    // W transpose + tf32 pre-round
    transpose_w_kernel<<<(D_IN * D_OUT + 255) / 256, 256>>>(W);

    // histogram + fused scan (independent of GEMM)
    hist_kernel<<<(E / 4 + 255) / 256, 256>>>(rowp, E);
    int nb = (M + SCAN_BLK - 1) / SCAN_BLK;
    scan_fused_kernel<<<nb, SCAN_BLK>>>(M, E);

    // tensor-core GEMM + fused attention projections (2-stage cp.async)
    static const size_t smem_bytes = 4 * TILE_F * sizeof(float);   // 73728
    cudaFuncSetAttribute(gemm_tf32_kernel,
                         cudaFuncAttributeMaxDynamicSharedMemorySize,
                         (int)smem_bytes);
    int gblocks = (M + 127) / 128;
    gemm_tf32_kernel<<<gblocks, 256, smem_bytes>>>(features, b, wa1, wa2, ba1, ba2, M);

    // scatter (col, exp-weight) into CSR segments
    int eblocks = (E + 255) / 256;
    scatter_kernel<<<eblocks, 256>>>(rowp, colp, E);

    // gather SpMM (fp16 h)
    long long total_threads = (long long)M * 32;
    int mblocks = (int)((total_threads + 255) / 256);
    spmm_csr_kernel<<<mblocks, 256>>>(out, M);
}

// round 7
// speedup vs baseline: 2.9809x; 1.0824x over previous
#include <cuda_runtime.h>
#include <cuda_fp16.h>
#include <cstdint>
#include <cstddef>

#define D_IN  256
#define D_OUT 128
#define MAX_N 100000
#define MAX_E 1600000
#define SCAN_BLK 1024
#define VALID_FLAG (1u << 30)

// Scratch (device globals: no allocation allowed)
__device__ uint32_t g_hh[(size_t)MAX_N * (D_OUT / 2)];  // h as fp16x2, 25.6 MB
__device__ float  g_a1[MAX_N];
__device__ float  g_a2[MAX_N];
__device__ float  g_Wt[D_OUT * D_IN];           // W transposed + pre-rounded to tf32
__device__ int    g_count[MAX_N];
__device__ unsigned g_bsum[128];                // block totals | VALID_FLAG
__device__ int    g_rowstart[MAX_N + 1];
__device__ int    g_pos[MAX_N];
__device__ float2 g_scw[MAX_E];                 // packed (col-as-float-bits, expw)

// ---------------- ldmatrix / mma / cp.async wrappers ----------------
__device__ __forceinline__ uint32_t smem_u32(const void* p) {
    return (uint32_t)__cvta_generic_to_shared(p);
}
__device__ __forceinline__ void ldsm_x4(uint32_t& r0, uint32_t& r1,
                                        uint32_t& r2, uint32_t& r3, uint32_t addr) {
    asm volatile("ldmatrix.sync.aligned.m8n8.x4.shared.b16 {%0,%1,%2,%3}, [%4];"
                 : "=r"(r0), "=r"(r1), "=r"(r2), "=r"(r3) : "r"(addr));
}
__device__ __forceinline__ void mma_tf32(float* d, const uint32_t* a, const uint32_t* b) {
    asm volatile(
        "mma.sync.aligned.m16n8k8.row.col.f32.tf32.tf32.f32 "
        "{%0,%1,%2,%3}, {%4,%5,%6,%7}, {%8,%9}, {%0,%1,%2,%3};"
        : "+f"(d[0]), "+f"(d[1]), "+f"(d[2]), "+f"(d[3])
        : "r"(a[0]), "r"(a[1]), "r"(a[2]), "r"(a[3]), "r"(b[0]), "r"(b[1]));
}
__device__ __forceinline__ uint32_t tf32_rna(float f) {
    uint32_t r;
    asm("cvt.rna.tf32.f32 %0, %1;" : "=r"(r) : "f"(f));
    return r;
}
__device__ __forceinline__ uint32_t f16x2_rn(float lo, float hi) {
    uint32_t r;   // %1 -> high half, %2 -> low half
    asm("cvt.rn.f16x2.f32 %0, %1, %2;" : "=r"(r) : "f"(hi), "f"(lo));
    return r;
}
__device__ __forceinline__ void cp_async16(uint32_t dst, const void* src, int src_bytes) {
    asm volatile("cp.async.cg.shared.global [%0], [%1], 16, %2;"
                 :: "r"(dst), "l"(src), "r"(src_bytes));
}
__device__ __forceinline__ void cp_commit() {
    asm volatile("cp.async.commit_group;");
}
template <int N>
__device__ __forceinline__ void cp_wait() {
    asm volatile("cp.async.wait_group %0;" :: "n"(N));
}

// ---------------- transpose W + pre-round to tf32 (rna, unbiased) -----------
__global__ void __launch_bounds__(256) transpose_w_kernel(const float* __restrict__ W)
{
    int idx = blockIdx.x * 256 + threadIdx.x;   // 32768 total
    if (idx < D_IN * D_OUT) {
        int k = idx / D_OUT;
        int n = idx % D_OUT;
        uint32_t t = tf32_rna(W[idx]);
        g_Wt[n * D_IN + k] = __uint_as_float(t);
    }
}

// ---------------- tf32 tensor-core GEMM, 3-stage cp.async pipeline ----------
// h = X@W + b -> fp16; fused a1 = h@wa1+ba1, a2 = h@wa2+ba2 (atomic partials).
#define SMPAD   36
#define TILE_F  (128 * SMPAD)
#define NKT     (D_IN / 32)
#define NSTAGE  3

__global__ void __launch_bounds__(256) gemm_tf32_kernel(
    const float* __restrict__ A,
    const float* __restrict__ bias,
    const float* __restrict__ wa1, const float* __restrict__ wa2,
    const float* __restrict__ ba1, const float* __restrict__ ba2,
    int M)
{
    extern __shared__ float sm[];
    float* Asm = sm;
    float* Bsm = sm + NSTAGE * TILE_F;

    const int tid  = threadIdx.x;
    const int lane = tid & 31;
    const int wid  = tid >> 5;
    const int wm   = wid & 3;
    const int wn   = wid >> 2;
    const int row0 = blockIdx.x * 128;
    const int mrow = wm * 32;
    const int ncol = wn * 64;

    const int grp = lane >> 3;
    const int rr  = lane & 7;

    int lr[4], lc[4];
#pragma unroll
    for (int i = 0; i < 4; i++) {
        int idx = tid + i * 256;
        lr[i] = idx >> 3;
        lc[i] = (idx & 7) * 4;
    }

    auto load_tiles = [&](int stage, int k0) {
        float* Ad = Asm + stage * TILE_F;
        float* Bd = Bsm + stage * TILE_F;
#pragma unroll
        for (int i = 0; i < 4; i++) {
            int gr = row0 + lr[i];
            int ok = (gr < M) ? 16 : 0;
            const float* src = A + (size_t)((gr < M) ? gr : 0) * D_IN + k0 + lc[i];
            cp_async16(smem_u32(Ad + lr[i] * SMPAD + lc[i]), src, ok);
        }
#pragma unroll
        for (int i = 0; i < 4; i++) {
            const float* src = g_Wt + (size_t)lr[i] * D_IN + k0 + lc[i];
            cp_async16(smem_u32(Bd + lr[i] * SMPAD + lc[i]), src, 16);
        }
        cp_commit();
    };

    float c[2][8][4];
#pragma unroll
    for (int mt = 0; mt < 2; mt++)
#pragma unroll
        for (int nt = 0; nt < 8; nt++)
#pragma unroll
            for (int i = 0; i < 4; i++) c[mt][nt][i] = 0.f;

    load_tiles(0, 0);
    load_tiles(1, 32);

    for (int kt = 0; kt < NKT; kt++) {
        if (kt + 2 < NKT) {
            load_tiles((kt + 2) % NSTAGE, (kt + 2) * 32);
            cp_wait<2>();
        } else if (kt + 1 < NKT) {
            cp_wait<1>();
        } else {
            cp_wait<0>();
        }
        __syncthreads();

        const float* As = Asm + (kt % NSTAGE) * TILE_F;
        const float* Bt = Bsm + (kt % NSTAGE) * TILE_F;

#pragma unroll
        for (int ks = 0; ks < 32; ks += 8) {
            uint32_t a[2][4];
#pragma unroll
            for (int mt = 0; mt < 2; mt++) {
                uint32_t addr = smem_u32(
                    As + (mrow + mt * 16 + rr + 8 * (grp & 1)) * SMPAD + ks + 4 * (grp >> 1));
                ldsm_x4(a[mt][0], a[mt][1], a[mt][2], a[mt][3], addr);
                // unbiased rounding of A operands (kills tf32 truncation bias)
#pragma unroll
                for (int q = 0; q < 4; q++)
                    a[mt][q] = tf32_rna(__uint_as_float(a[mt][q]));
            }
            uint32_t b[8][2];   // B pre-rounded in transpose kernel
#pragma unroll
            for (int p = 0; p < 4; p++) {
                int n0 = ncol + p * 16;
                uint32_t addr = smem_u32(
                    Bt + (n0 + rr + 8 * (grp >> 1)) * SMPAD + ks + 4 * (grp & 1));
                ldsm_x4(b[2 * p][0], b[2 * p][1], b[2 * p + 1][0], b[2 * p + 1][1], addr);
            }
#pragma unroll
            for (int mt = 0; mt < 2; mt++)
#pragma unroll
                for (int nt = 0; nt < 8; nt++)
                    mma_tf32(c[mt][nt], a[mt], b[nt]);
        }
        __syncthreads();
    }

    // ---------------- epilogue: fp16 h store + fused a1/a2 ----------------
    const float ba1v = ba1[0];
    const float ba2v = ba2[0];
    const int qrow = lane >> 2;
    const int qcol = 2 * (lane & 3);

#pragma unroll
    for (int mt = 0; mt < 2; mt++) {
        int grlo = row0 + mrow + mt * 16 + qrow;
        int grhi = grlo + 8;
        float p1lo = 0.f, p2lo = 0.f, p1hi = 0.f, p2hi = 0.f;
#pragma unroll
        for (int nt = 0; nt < 8; nt++) {
            int gc = ncol + nt * 8 + qcol;
            float bc0 = bias[gc], bc1 = bias[gc + 1];
            float v0 = c[mt][nt][0] + bc0;
            float v1 = c[mt][nt][1] + bc1;
            float v2 = c[mt][nt][2] + bc0;
            float v3 = c[mt][nt][3] + bc1;
            if (grlo < M)
                g_hh[(size_t)grlo * (D_OUT / 2) + gc / 2] = f16x2_rn(v0, v1);
            if (grhi < M)
                g_hh[(size_t)grhi * (D_OUT / 2) + gc / 2] = f16x2_rn(v2, v3);
            float w1a = wa1[gc], w1b = wa1[gc + 1];
            float w2a = wa2[gc], w2b = wa2[gc + 1];
            p1lo += v0 * w1a + v1 * w1b;
            p2lo += v0 * w2a + v1 * w2b;
            p1hi += v2 * w1a + v3 * w1b;
            p2hi += v2 * w2a + v3 * w2b;
        }
#pragma unroll
        for (int o = 1; o < 4; o <<= 1) {
            p1lo += __shfl_xor_sync(0xffffffffu, p1lo, o);
            p2lo += __shfl_xor_sync(0xffffffffu, p2lo, o);
            p1hi += __shfl_xor_sync(0xffffffffu, p1hi, o);
            p2hi += __shfl_xor_sync(0xffffffffu, p2hi, o);
        }
        if ((lane & 3) == 0) {
            if (wn == 0) {
                p1lo += ba1v; p2lo += ba2v;
                p1hi += ba1v; p2hi += ba2v;
            }
            if (grlo < M) {
                atomicAdd(&g_a1[grlo], p1lo);
                atomicAdd(&g_a2[grlo], p2lo);
            }
            if (grhi < M) {
                atomicAdd(&g_a1[grhi], p1hi);
                atomicAdd(&g_a2[grhi], p2hi);
            }
        }
    }
}

// ---------------- histogram of destination rows (vectorized) ----------------
__global__ void __launch_bounds__(256) hist_kernel(
    const int* __restrict__ row, int E)
{
    int t = blockIdx.x * blockDim.x + threadIdx.x;
    int nq = E >> 2;
    if (t < nq) {
        int4 v = reinterpret_cast<const int4*>(row)[t];
        atomicAdd(&g_count[v.x], 1);
        atomicAdd(&g_count[v.y], 1);
        atomicAdd(&g_count[v.z], 1);
        atomicAdd(&g_count[v.w], 1);
    }
    int rem = nq * 4 + t;
    if (t < (E & 3) && rem < E) atomicAdd(&g_count[row[rem]], 1);
}

// ---------------- fused single-pass exclusive scan (inter-block lookback) ----
__device__ __forceinline__ void block_scan_1024(int v, int tid, int& excl, int& total)
{
    int lane = tid & 31, wid = tid >> 5;
    int x = v;
#pragma unroll
    for (int o = 1; o < 32; o <<= 1) {
        int y = __shfl_up_sync(0xffffffffu, x, o);
        if (lane >= o) x += y;
    }
    __shared__ int ws[32];
    if (lane == 31) ws[wid] = x;
    __syncthreads();
    if (wid == 0) {
        int s = ws[lane];
#pragma unroll
        for (int o = 1; o < 32; o <<= 1) {
            int y = __shfl_up_sync(0xffffffffu, s, o);
            if (lane >= o) s += y;
        }
        ws[lane] = s;
    }
    __syncthreads();
    int warp_off = (wid > 0) ? ws[wid - 1] : 0;
    int incl = warp_off + x;
    excl  = incl - v;
    total = ws[31];
}

__global__ void __launch_bounds__(SCAN_BLK) scan_fused_kernel(int n, int E)
{
    int i = blockIdx.x * SCAN_BLK + threadIdx.x;
    int v = (i < n) ? g_count[i] : 0;
    int excl, total;
    block_scan_1024(v, threadIdx.x, excl, total);

    if (threadIdx.x == 0)
        atomicExch(&g_bsum[blockIdx.x], (unsigned)total | VALID_FLAG);

    int part = 0;
    if (threadIdx.x < blockIdx.x) {
        unsigned w;
        do { w = atomicAdd(&g_bsum[threadIdx.x], 0u); } while (!(w & VALID_FLAG));
        part = (int)(w & (VALID_FLAG - 1));
    }
    int lane = threadIdx.x & 31, wid = threadIdx.x >> 5;
#pragma unroll
    for (int o = 16; o > 0; o >>= 1)
        part += __shfl_xor_sync(0xffffffffu, part, o);
    __shared__ int rs[32];
    __syncthreads();
    if (lane == 0) rs[wid] = part;
    __syncthreads();
    if (wid == 0) {
        int s = rs[lane];
#pragma unroll
        for (int o = 16; o > 0; o >>= 1)
            s += __shfl_xor_sync(0xffffffffu, s, o);
        rs[0] = s;
    }
    __syncthreads();
    int offset = rs[0];

    if (i < n) {
        int vv = excl + offset;
        g_rowstart[i] = vv;
        g_pos[i]      = vv;
        if (i == n - 1) g_rowstart[n] = E;
    }
}

// ---------------- scatter into CSR + edge scores ----------------
__global__ void __launch_bounds__(256) scatter_kernel(
    const int* __restrict__ row, const int* __restrict__ col, int E)
{
    int e = blockIdx.x * blockDim.x + threadIdx.x;
    if (e < E) {
        int r = row[e];
        int c = col[e];
        float s = g_a1[r] + g_a2[c];
        s = (s > 0.f) ? s : 0.01f * s;       // LeakyReLU(0.01)
        float w = __expf(s);                  // exp(s)/sum(exp(s)) == softmax(s)
        int p = atomicAdd(&g_pos[r], 1);
        g_scw[p] = make_float2(__int_as_float(c), w);
    }
}

// ---------------- CSR gather SpMM: one warp per row, fp16 h ----------------
__device__ __forceinline__ void f16x2_unpack(uint32_t u, float& lo, float& hi) {
    __half2 h = *reinterpret_cast<__half2*>(&u);
    float2 f = __half22float2(h);
    lo = f.x;
    hi = f.y;
}

__global__ void __launch_bounds__(256) spmm_csr_kernel(
    float* __restrict__ out, int M)
{
    int r    = (blockIdx.x * blockDim.x + threadIdx.x) >> 5;
    int lane = threadIdx.x & 31;
    if (r >= M) return;

    int start = g_rowstart[r];
    int end   = g_rowstart[r + 1];

    float4 acc = make_float4(0.f, 0.f, 0.f, 0.f);

    if (end > start) {
        const uint2* __restrict__ h2 = reinterpret_cast<const uint2*>(g_hh);
        float dsum = 0.f;   // identical in every lane

        for (int base = start; base < end; base += 32) {
            int   i = base + lane;
            int   cc = 0;
            float ww = 0.f;
            if (i < end) {
                float2 e = g_scw[i];
                cc = __float_as_int(e.x);
                ww = e.y;
            }
            int n = end - base; if (n > 32) n = 32;

            int j = 0;
            for (; j + 4 <= n; j += 4) {
                int   c0 = __shfl_sync(0xffffffffu, cc, j);
                int   c1 = __shfl_sync(0xffffffffu, cc, j + 1);
                int   c2 = __shfl_sync(0xffffffffu, cc, j + 2);
                int   c3 = __shfl_sync(0xffffffffu, cc, j + 3);
                float w0 = __shfl_sync(0xffffffffu, ww, j);
                float w1 = __shfl_sync(0xffffffffu, ww, j + 1);
                float w2 = __shfl_sync(0xffffffffu, ww, j + 2);
                float w3 = __shfl_sync(0xffffffffu, ww, j + 3);
                uint2 u0 = h2[(size_t)c0 * 32 + lane];
                uint2 u1 = h2[(size_t)c1 * 32 + lane];
                uint2 u2 = h2[(size_t)c2 * 32 + lane];
                uint2 u3 = h2[(size_t)c3 * 32 + lane];
                dsum += w0 + w1 + w2 + w3;
                float ax, ay, az, aw;
                f16x2_unpack(u0.x, ax, ay); f16x2_unpack(u0.y, az, aw);
                acc.x = fmaf(w0, ax, acc.x); acc.y = fmaf(w0, ay, acc.y);
                acc.z = fmaf(w0, az, acc.z); acc.w = fmaf(w0, aw, acc.w);
                f16x2_unpack(u1.x, ax, ay); f16x2_unpack(u1.y, az, aw);
                acc.x = fmaf(w1, ax, acc.x); acc.y = fmaf(w1, ay, acc.y);
                acc.z = fmaf(w1, az, acc.z); acc.w = fmaf(w1, aw, acc.w);
                f16x2_unpack(u2.x, ax, ay); f16x2_unpack(u2.y, az, aw);
                acc.x = fmaf(w2, ax, acc.x); acc.y = fmaf(w2, ay, acc.y);
                acc.z = fmaf(w2, az, acc.z); acc.w = fmaf(w2, aw, acc.w);
                f16x2_unpack(u3.x, ax, ay); f16x2_unpack(u3.y, az, aw);
                acc.x = fmaf(w3, ax, acc.x); acc.y = fmaf(w3, ay, acc.y);
                acc.z = fmaf(w3, az, acc.z); acc.w = fmaf(w3, aw, acc.w);
            }
            for (; j < n; j++) {
                int   cj = __shfl_sync(0xffffffffu, cc, j);
                float wj = __shfl_sync(0xffffffffu, ww, j);
                uint2 u = h2[(size_t)cj * 32 + lane];
                dsum += wj;
                float ax, ay, az, aw;
                f16x2_unpack(u.x, ax, ay); f16x2_unpack(u.y, az, aw);
                acc.x = fmaf(wj, ax, acc.x); acc.y = fmaf(wj, ay, acc.y);
                acc.z = fmaf(wj, az, acc.z); acc.w = fmaf(wj, aw, acc.w);
            }
        }
        float inv = 1.0f / dsum;
        acc.x *= inv; acc.y *= inv; acc.z *= inv; acc.w *= inv;
    }
    *reinterpret_cast<float4*>(out + (size_t)r * D_OUT + lane * 4) = acc;
}

// ---------------- launch: fork/join CSR build alongside GEMM ----------------
extern "C" void kernel_launch(void* const* d_in, const int* in_sizes, int n_in,
                              void* d_out, int out_size)
{
    const float* features = (const float*)d_in[0];
    const int*   ei       = (const int*)d_in[1];
    const float* W        = (const float*)d_in[2];
    const float* b        = (const float*)d_in[3];
    const float* wa1      = (const float*)d_in[4];
    const float* ba1      = (const float*)d_in[5];
    const float* wa2      = (const float*)d_in[6];
    const float* ba2      = (const float*)d_in[7];

    const int M = in_sizes[0] / D_IN;   // 100000
    const int E = in_sizes[1] / 2;      // 1600000
    float* out = (float*)d_out;

    const int* rowp = ei;
    const int* colp = ei + E;

    // lazily created once on the (uncaptured) correctness call; reused during capture
    static cudaStream_t s1 = nullptr;
    static cudaEvent_t  evFork = nullptr, evJoin = nullptr;
    if (s1 == nullptr) {
        cudaStreamCreateWithFlags(&s1, cudaStreamNonBlocking);
        cudaEventCreateWithFlags(&evFork, cudaEventDisableTiming);
        cudaEventCreateWithFlags(&evJoin, cudaEventDisableTiming);
    }

    void* p = nullptr;

    // fork: CSR build on s1
    cudaEventRecord(evFork, 0);
    cudaStreamWaitEvent(s1, evFork, 0);

    cudaGetSymbolAddress(&p, g_count);
    cudaMemsetAsync(p, 0, (size_t)M * sizeof(int), s1);
    cudaGetSymbolAddress(&p, g_bsum);
    cudaMemsetAsync(p, 0, 128 * sizeof(unsigned), s1);
    hist_kernel<<<(E / 4 + 255) / 256, 256, 0, s1>>>(rowp, E);
    int nb = (M + SCAN_BLK - 1) / SCAN_BLK;
    scan_fused_kernel<<<nb, SCAN_BLK, 0, s1>>>(M, E);
    cudaEventRecord(evJoin, s1);

    // main stream: GEMM path
    cudaGetSymbolAddress(&p, g_a1);
    cudaMemsetAsync(p, 0, (size_t)M * sizeof(float), 0);
    cudaGetSymbolAddress(&p, g_a2);
    cudaMemsetAsync(p, 0, (size_t)M * sizeof(float), 0);
    transpose_w_kernel<<<(D_IN * D_OUT + 255) / 256, 256>>>(W);

    static const size_t smem_bytes = 2 * NSTAGE * TILE_F * sizeof(float);  // 110592
    cudaFuncSetAttribute(gemm_tf32_kernel,
                         cudaFuncAttributeMaxDynamicSharedMemorySize,
                         (int)smem_bytes);
    int gblocks = (M + 127) / 128;
    gemm_tf32_kernel<<<gblocks, 256, smem_bytes>>>(features, b, wa1, wa2, ba1, ba2, M);

    // join: scatter needs a1/a2 (main) + g_pos (s1)
    cudaStreamWaitEvent(0, evJoin, 0);

    int eblocks = (E + 255) / 256;
    scatter_kernel<<<eblocks, 256>>>(rowp, colp, E);

    long long total_threads = (long long)M * 32;
    int mblocks = (int)((total_threads + 255) / 256);
    spmm_csr_kernel<<<mblocks, 256>>>(out, M);
}

// round 9
// speedup vs baseline: 3.0267x; 1.0154x over previous
#include <cuda_runtime.h>
#include <cuda_fp16.h>
#include <cstdint>
#include <cstddef>

#define D_IN  256
#define D_OUT 128
#define MAX_N 100000
#define MAX_E 1600000
#define SCAN_BLK 1024
#define VALID_FLAG (1u << 30)

// Scratch (device globals: no allocation allowed)
__device__ uint32_t g_hh[(size_t)MAX_N * (D_OUT / 2)];  // h as fp16x2, 25.6 MB
__device__ float  g_a1[MAX_N];
__device__ float  g_a2[MAX_N];
__device__ float  g_Wt[D_OUT * D_IN];           // W transposed + pre-rounded to tf32
__device__ int    g_count[MAX_N];
__device__ unsigned g_bsum[128];                // block totals | VALID_FLAG
__device__ int    g_rowstart[MAX_N + 1];
__device__ int    g_pos[MAX_N];
__device__ float2 g_scw[MAX_E];                 // packed (col-as-float-bits, expw)

// ---------------- ldmatrix / mma / cp.async wrappers ----------------
__device__ __forceinline__ uint32_t smem_u32(const void* p) {
    return (uint32_t)__cvta_generic_to_shared(p);
}
__device__ __forceinline__ void ldsm_x4(uint32_t& r0, uint32_t& r1,
                                        uint32_t& r2, uint32_t& r3, uint32_t addr) {
    asm volatile("ldmatrix.sync.aligned.m8n8.x4.shared.b16 {%0,%1,%2,%3}, [%4];"
                 : "=r"(r0), "=r"(r1), "=r"(r2), "=r"(r3) : "r"(addr));
}
__device__ __forceinline__ void mma_tf32(float* d, const uint32_t* a, const uint32_t* b) {
    asm volatile(
        "mma.sync.aligned.m16n8k8.row.col.f32.tf32.tf32.f32 "
        "{%0,%1,%2,%3}, {%4,%5,%6,%7}, {%8,%9}, {%0,%1,%2,%3};"
        : "+f"(d[0]), "+f"(d[1]), "+f"(d[2]), "+f"(d[3])
        : "r"(a[0]), "r"(a[1]), "r"(a[2]), "r"(a[3]), "r"(b[0]), "r"(b[1]));
}
__device__ __forceinline__ uint32_t tf32_rna(float f) {
    uint32_t r;
    asm("cvt.rna.tf32.f32 %0, %1;" : "=r"(r) : "f"(f));
    return r;
}
__device__ __forceinline__ uint32_t f16x2_rn(float lo, float hi) {
    uint32_t r;   // %1 -> high half, %2 -> low half
    asm("cvt.rn.f16x2.f32 %0, %1, %2;" : "=r"(r) : "f"(hi), "f"(lo));
    return r;
}
__device__ __forceinline__ void cp_async16(uint32_t dst, const void* src, int src_bytes) {
    asm volatile("cp.async.cg.shared.global [%0], [%1], 16, %2;"
                 :: "r"(dst), "l"(src), "r"(src_bytes));
}
__device__ __forceinline__ void cp_commit() {
    asm volatile("cp.async.commit_group;");
}
template <int N>
__device__ __forceinline__ void cp_wait() {
    asm volatile("cp.async.wait_group %0;" :: "n"(N));
}

// ---------------- transpose W + pre-round to tf32 (rna, unbiased) -----------
__global__ void __launch_bounds__(256) transpose_w_kernel(const float* __restrict__ W)
{
    int idx = blockIdx.x * 256 + threadIdx.x;   // 32768 total
    if (idx < D_IN * D_OUT) {
        int k = idx / D_OUT;
        int n = idx % D_OUT;
        uint32_t t = tf32_rna(W[idx]);
        g_Wt[n * D_IN + k] = __uint_as_float(t);
    }
}

// ---------------- tf32 tensor-core GEMM, 3-stage cp.async pipeline ----------
// h = X@W + b -> fp16; fused a1 = h@wa1+ba1, a2 = h@wa2+ba2 (atomic partials).
// A fragments are used truncated (HW tf32 truncation); W is rna-pre-rounded,
// keeping the coherent bias to ~2^-11 from A only (measured-safe vs 1e-3).
#define SMPAD   36
#define TILE_F  (128 * SMPAD)
#define NKT     (D_IN / 32)
#define NSTAGE  3

__global__ void __launch_bounds__(256) gemm_tf32_kernel(
    const float* __restrict__ A,
    const float* __restrict__ bias,
    const float* __restrict__ wa1, const float* __restrict__ wa2,
    const float* __restrict__ ba1, const float* __restrict__ ba2,
    int M)
{
    extern __shared__ float sm[];
    float* Asm = sm;
    float* Bsm = sm + NSTAGE * TILE_F;

    const int tid  = threadIdx.x;
    const int lane = tid & 31;
    const int wid  = tid >> 5;
    const int wm   = wid & 3;
    const int wn   = wid >> 2;
    const int row0 = blockIdx.x * 128;
    const int mrow = wm * 32;
    const int ncol = wn * 64;

    const int grp = lane >> 3;
    const int rr  = lane & 7;

    int lr[4], lc[4];
#pragma unroll
    for (int i = 0; i < 4; i++) {
        int idx = tid + i * 256;
        lr[i] = idx >> 3;
        lc[i] = (idx & 7) * 4;
    }

    auto load_tiles = [&](int stage, int k0) {
        float* Ad = Asm + stage * TILE_F;
        float* Bd = Bsm + stage * TILE_F;
#pragma unroll
        for (int i = 0; i < 4; i++) {
            int gr = row0 + lr[i];
            int ok = (gr < M) ? 16 : 0;
            const float* src = A + (size_t)((gr < M) ? gr : 0) * D_IN + k0 + lc[i];
            cp_async16(smem_u32(Ad + lr[i] * SMPAD + lc[i]), src, ok);
        }
#pragma unroll
        for (int i = 0; i < 4; i++) {
            const float* src = g_Wt + (size_t)lr[i] * D_IN + k0 + lc[i];
            cp_async16(smem_u32(Bd + lr[i] * SMPAD + lc[i]), src, 16);
        }
        cp_commit();
    };

    float c[2][8][4];
#pragma unroll
    for (int mt = 0; mt < 2; mt++)
#pragma unroll
        for (int nt = 0; nt < 8; nt++)
#pragma unroll
            for (int i = 0; i < 4; i++) c[mt][nt][i] = 0.f;

    load_tiles(0, 0);
    load_tiles(1, 32);

    for (int kt = 0; kt < NKT; kt++) {
        if (kt + 1 < NKT) cp_wait<1>(); else cp_wait<0>();
        __syncthreads();
        // prefetch issued AFTER the barrier: stage (kt+2)%3 == (kt-1)%3, whose
        // readers all passed this barrier -> no second barrier needed per tile.
        if (kt + 2 < NKT)
            load_tiles((kt + 2) % NSTAGE, (kt + 2) * 32);

        const float* As = Asm + (kt % NSTAGE) * TILE_F;
        const float* Bt = Bsm + (kt % NSTAGE) * TILE_F;

#pragma unroll
        for (int ks = 0; ks < 32; ks += 8) {
            uint32_t a[2][4];
#pragma unroll
            for (int mt = 0; mt < 2; mt++) {
                uint32_t addr = smem_u32(
                    As + (mrow + mt * 16 + rr + 8 * (grp & 1)) * SMPAD + ks + 4 * (grp >> 1));
                ldsm_x4(a[mt][0], a[mt][1], a[mt][2], a[mt][3], addr);
            }
            uint32_t b[8][2];   // B pre-rounded (rna) in transpose kernel
#pragma unroll
            for (int p = 0; p < 4; p++) {
                int n0 = ncol + p * 16;
                uint32_t addr = smem_u32(
                    Bt + (n0 + rr + 8 * (grp >> 1)) * SMPAD + ks + 4 * (grp & 1));
                ldsm_x4(b[2 * p][0], b[2 * p][1], b[2 * p + 1][0], b[2 * p + 1][1], addr);
            }
#pragma unroll
            for (int mt = 0; mt < 2; mt++)
#pragma unroll
                for (int nt = 0; nt < 8; nt++)
                    mma_tf32(c[mt][nt], a[mt], b[nt]);
        }
    }

    // ---------------- epilogue: fp16 h store + fused a1/a2 ----------------
    const float ba1v = ba1[0];
    const float ba2v = ba2[0];
    const int qrow = lane >> 2;
    const int qcol = 2 * (lane & 3);

#pragma unroll
    for (int mt = 0; mt < 2; mt++) {
        int grlo = row0 + mrow + mt * 16 + qrow;
        int grhi = grlo + 8;
        float p1lo = 0.f, p2lo = 0.f, p1hi = 0.f, p2hi = 0.f;
#pragma unroll
        for (int nt = 0; nt < 8; nt++) {
            int gc = ncol + nt * 8 + qcol;
            float bc0 = bias[gc], bc1 = bias[gc + 1];
            float v0 = c[mt][nt][0] + bc0;
            float v1 = c[mt][nt][1] + bc1;
            float v2 = c[mt][nt][2] + bc0;
            float v3 = c[mt][nt][3] + bc1;
            if (grlo < M)
                g_hh[(size_t)grlo * (D_OUT / 2) + gc / 2] = f16x2_rn(v0, v1);
            if (grhi < M)
                g_hh[(size_t)grhi * (D_OUT / 2) + gc / 2] = f16x2_rn(v2, v3);
            float w1a = wa1[gc], w1b = wa1[gc + 1];
            float w2a = wa2[gc], w2b = wa2[gc + 1];
            p1lo += v0 * w1a + v1 * w1b;
            p2lo += v0 * w2a + v1 * w2b;
            p1hi += v2 * w1a + v3 * w1b;
            p2hi += v2 * w2a + v3 * w2b;
        }
#pragma unroll
        for (int o = 1; o < 4; o <<= 1) {
            p1lo += __shfl_xor_sync(0xffffffffu, p1lo, o);
            p2lo += __shfl_xor_sync(0xffffffffu, p2lo, o);
            p1hi += __shfl_xor_sync(0xffffffffu, p1hi, o);
            p2hi += __shfl_xor_sync(0xffffffffu, p2hi, o);
        }
        if ((lane & 3) == 0) {
            if (wn == 0) {
                p1lo += ba1v; p2lo += ba2v;
                p1hi += ba1v; p2hi += ba2v;
            }
            if (grlo < M) {
                atomicAdd(&g_a1[grlo], p1lo);
                atomicAdd(&g_a2[grlo], p2lo);
            }
            if (grhi < M) {
                atomicAdd(&g_a1[grhi], p1hi);
                atomicAdd(&g_a2[grhi], p2hi);
            }
        }
    }
}

// ---------------- histogram of destination rows (vectorized) ----------------
__global__ void __launch_bounds__(256) hist_kernel(
    const int* __restrict__ row, int E)
{
    int t = blockIdx.x * blockDim.x + threadIdx.x;
    int nq = E >> 2;
    if (t < nq) {
        int4 v = reinterpret_cast<const int4*>(row)[t];
        atomicAdd(&g_count[v.x], 1);
        atomicAdd(&g_count[v.y], 1);
        atomicAdd(&g_count[v.z], 1);
        atomicAdd(&g_count[v.w], 1);
    }
    int rem = nq * 4 + t;
    if (t < (E & 3) && rem < E) atomicAdd(&g_count[row[rem]], 1);
}

// ---------------- fused single-pass exclusive scan (inter-block lookback) ----
__device__ __forceinline__ void block_scan_1024(int v, int tid, int& excl, int& total)
{
    int lane = tid & 31, wid = tid >> 5;
    int x = v;
#pragma unroll
    for (int o = 1; o < 32; o <<= 1) {
        int y = __shfl_up_sync(0xffffffffu, x, o);
        if (lane >= o) x += y;
    }
    __shared__ int ws[32];
    if (lane == 31) ws[wid] = x;
    __syncthreads();
    if (wid == 0) {
        int s = ws[lane];
#pragma unroll
        for (int o = 1; o < 32; o <<= 1) {
            int y = __shfl_up_sync(0xffffffffu, s, o);
            if (lane >= o) s += y;
        }
        ws[lane] = s;
    }
    __syncthreads();
    int warp_off = (wid > 0) ? ws[wid - 1] : 0;
    int incl = warp_off + x;
    excl  = incl - v;
    total = ws[31];
}

__global__ void __launch_bounds__(SCAN_BLK) scan_fused_kernel(int n, int E)
{
    int i = blockIdx.x * SCAN_BLK + threadIdx.x;
    int v = (i < n) ? g_count[i] : 0;
    int excl, total;
    block_scan_1024(v, threadIdx.x, excl, total);

    if (threadIdx.x == 0)
        atomicExch(&g_bsum[blockIdx.x], (unsigned)total | VALID_FLAG);

    int part = 0;
    if (threadIdx.x < blockIdx.x) {
        unsigned w;
        do { w = atomicAdd(&g_bsum[threadIdx.x], 0u); } while (!(w & VALID_FLAG));
        part = (int)(w & (VALID_FLAG - 1));
    }
    int lane = threadIdx.x & 31, wid = threadIdx.x >> 5;
#pragma unroll
    for (int o = 16; o > 0; o >>= 1)
        part += __shfl_xor_sync(0xffffffffu, part, o);
    __shared__ int rs[32];
    __syncthreads();
    if (lane == 0) rs[wid] = part;
    __syncthreads();
    if (wid == 0) {
        int s = rs[lane];
#pragma unroll
        for (int o = 16; o > 0; o >>= 1)
            s += __shfl_xor_sync(0xffffffffu, s, o);
        rs[0] = s;
    }
    __syncthreads();
    int offset = rs[0];

    if (i < n) {
        int vv = excl + offset;
        g_rowstart[i] = vv;
        g_pos[i]      = vv;
        if (i == n - 1) g_rowstart[n] = E;
    }
}

// ---------------- scatter into CSR + edge scores ----------------
__global__ void __launch_bounds__(256) scatter_kernel(
    const int* __restrict__ row, const int* __restrict__ col, int E)
{
    int e = blockIdx.x * blockDim.x + threadIdx.x;
    if (e < E) {
        int r = row[e];
        int c = col[e];
        float s = g_a1[r] + g_a2[c];
        s = (s > 0.f) ? s : 0.01f * s;       // LeakyReLU(0.01)
        float w = __expf(s);                  // exp(s)/sum(exp(s)) == softmax(s)
        int p = atomicAdd(&g_pos[r], 1);
        g_scw[p] = make_float2(__int_as_float(c), w);
    }
}

// ---------------- CSR gather SpMM: one warp per row, fp16 h ----------------
__device__ __forceinline__ void f16x2_unpack(uint32_t u, float& lo, float& hi) {
    __half2 h = *reinterpret_cast<__half2*>(&u);
    float2 f = __half22float2(h);
    lo = f.x;
    hi = f.y;
}

__global__ void __launch_bounds__(256) spmm_csr_kernel(
    float* __restrict__ out, int M)
{
    int r    = (blockIdx.x * blockDim.x + threadIdx.x) >> 5;
    int lane = threadIdx.x & 31;
    if (r >= M) return;

    int start = g_rowstart[r];
    int end   = g_rowstart[r + 1];

    float4 acc = make_float4(0.f, 0.f, 0.f, 0.f);

    if (end > start) {
        const uint2* __restrict__ h2 = reinterpret_cast<const uint2*>(g_hh);
        float dsum = 0.f;   // identical in every lane

        for (int base = start; base < end; base += 32) {
            int   i = base + lane;
            int   cc = 0;
            float ww = 0.f;
            if (i < end) {
                float2 e = g_scw[i];
                cc = __float_as_int(e.x);
                ww = e.y;
            }
            int n = end - base; if (n > 32) n = 32;

            int j = 0;
            for (; j + 4 <= n; j += 4) {
                int   c0 = __shfl_sync(0xffffffffu, cc, j);
                int   c1 = __shfl_sync(0xffffffffu, cc, j + 1);
                int   c2 = __shfl_sync(0xffffffffu, cc, j + 2);
                int   c3 = __shfl_sync(0xffffffffu, cc, j + 3);
                float w0 = __shfl_sync(0xffffffffu, ww, j);
                float w1 = __shfl_sync(0xffffffffu, ww, j + 1);
                float w2 = __shfl_sync(0xffffffffu, ww, j + 2);
                float w3 = __shfl_sync(0xffffffffu, ww, j + 3);
                uint2 u0 = h2[(size_t)c0 * 32 + lane];
                uint2 u1 = h2[(size_t)c1 * 32 + lane];
                uint2 u2 = h2[(size_t)c2 * 32 + lane];
                uint2 u3 = h2[(size_t)c3 * 32 + lane];
                dsum += w0 + w1 + w2 + w3;
                float ax, ay, az, aw;
                f16x2_unpack(u0.x, ax, ay); f16x2_unpack(u0.y, az, aw);
                acc.x = fmaf(w0, ax, acc.x); acc.y = fmaf(w0, ay, acc.y);
                acc.z = fmaf(w0, az, acc.z); acc.w = fmaf(w0, aw, acc.w);
                f16x2_unpack(u1.x, ax, ay); f16x2_unpack(u1.y, az, aw);
                acc.x = fmaf(w1, ax, acc.x); acc.y = fmaf(w1, ay, acc.y);
                acc.z = fmaf(w1, az, acc.z); acc.w = fmaf(w1, aw, acc.w);
                f16x2_unpack(u2.x, ax, ay); f16x2_unpack(u2.y, az, aw);
                acc.x = fmaf(w2, ax, acc.x); acc.y = fmaf(w2, ay, acc.y);
                acc.z = fmaf(w2, az, acc.z); acc.w = fmaf(w2, aw, acc.w);
                f16x2_unpack(u3.x, ax, ay); f16x2_unpack(u3.y, az, aw);
                acc.x = fmaf(w3, ax, acc.x); acc.y = fmaf(w3, ay, acc.y);
                acc.z = fmaf(w3, az, acc.z); acc.w = fmaf(w3, aw, acc.w);
            }
            for (; j < n; j++) {
                int   cj = __shfl_sync(0xffffffffu, cc, j);
                float wj = __shfl_sync(0xffffffffu, ww, j);
                uint2 u = h2[(size_t)cj * 32 + lane];
                dsum += wj;
                float ax, ay, az, aw;
                f16x2_unpack(u.x, ax, ay); f16x2_unpack(u.y, az, aw);
                acc.x = fmaf(wj, ax, acc.x); acc.y = fmaf(wj, ay, acc.y);
                acc.z = fmaf(wj, az, acc.z); acc.w = fmaf(wj, aw, acc.w);
            }
        }
        float inv = 1.0f / dsum;
        acc.x *= inv; acc.y *= inv; acc.z *= inv; acc.w *= inv;
    }
    *reinterpret_cast<float4*>(out + (size_t)r * D_OUT + lane * 4) = acc;
}

// ---------------- launch: fork/join CSR build alongside GEMM ----------------
extern "C" void kernel_launch(void* const* d_in, const int* in_sizes, int n_in,
                              void* d_out, int out_size)
{
    const float* features = (const float*)d_in[0];
    const int*   ei       = (const int*)d_in[1];
    const float* W        = (const float*)d_in[2];
    const float* b        = (const float*)d_in[3];
    const float* wa1      = (const float*)d_in[4];
    const float* ba1      = (const float*)d_in[5];
    const float* wa2      = (const float*)d_in[6];
    const float* ba2      = (const float*)d_in[7];

    const int M = in_sizes[0] / D_IN;   // 100000
    const int E = in_sizes[1] / 2;      // 1600000
    float* out = (float*)d_out;

    const int* rowp = ei;
    const int* colp = ei + E;

    // lazily created once on the (uncaptured) correctness call; reused during capture
    static cudaStream_t s1 = nullptr;
    static cudaEvent_t  evFork = nullptr, evJoin = nullptr;
    if (s1 == nullptr) {
        cudaStreamCreateWithFlags(&s1, cudaStreamNonBlocking);
        cudaEventCreateWithFlags(&evFork, cudaEventDisableTiming);
        cudaEventCreateWithFlags(&evJoin, cudaEventDisableTiming);
    }

    void* p = nullptr;

    // fork: CSR build on s1
    cudaEventRecord(evFork, 0);
    cudaStreamWaitEvent(s1, evFork, 0);

    cudaGetSymbolAddress(&p, g_count);
    cudaMemsetAsync(p, 0, (size_t)M * sizeof(int), s1);
    cudaGetSymbolAddress(&p, g_bsum);
    cudaMemsetAsync(p, 0, 128 * sizeof(unsigned), s1);
    hist_kernel<<<(E / 4 + 255) / 256, 256, 0, s1>>>(rowp, E);
    int nb = (M + SCAN_BLK - 1) / SCAN_BLK;
    scan_fused_kernel<<<nb, SCAN_BLK, 0, s1>>>(M, E);
    cudaEventRecord(evJoin, s1);

    // main stream: GEMM path
    cudaGetSymbolAddress(&p, g_a1);
    cudaMemsetAsync(p, 0, (size_t)M * sizeof(float), 0);
    cudaGetSymbolAddress(&p, g_a2);
    cudaMemsetAsync(p, 0, (size_t)M * sizeof(float), 0);
    transpose_w_kernel<<<(D_IN * D_OUT + 255) / 256, 256>>>(W);

    static const size_t smem_bytes = 2 * NSTAGE * TILE_F * sizeof(float);  // 110592
    cudaFuncSetAttribute(gemm_tf32_kernel,
                         cudaFuncAttributeMaxDynamicSharedMemorySize,
                         (int)smem_bytes);
    int gblocks = (M + 127) / 128;
    gemm_tf32_kernel<<<gblocks, 256, smem_bytes>>>(features, b, wa1, wa2, ba1, ba2, M);

    // join: scatter needs a1/a2 (main) + g_pos (s1)
    cudaStreamWaitEvent(0, evJoin, 0);

    int eblocks = (E + 255) / 256;
    scatter_kernel<<<eblocks, 256>>>(rowp, colp, E);

    long long total_threads = (long long)M * 32;
    int mblocks = (int)((total_threads + 255) / 256);
    spmm_csr_kernel<<<mblocks, 256>>>(out, M);
}